// round 5
// baseline (speedup 1.0000x reference)
#include <cuda_runtime.h>

#define TOK 16384
#define LSEQ 4096
#define NB 4
#define DMO 64      // input/output dim D
#define DM 128      // d_model of mamba (2D)
#define DI 256      // d_inner
#define DS 16       // d_state
#define DTR 8       // dt_rank
#define NCH 1024    // NB * DI channels
#define CHK 64      // chunk length
#define NG (LSEQ / CHK)   // 64 chunks
#define NUNIT (NCH * NG)  // 65536 units

typedef unsigned long long ull;

__device__ __forceinline__ ull pk2(float a, float b) {
    ull r; asm("mov.b64 %0, {%1, %2};" : "=l"(r) : "f"(a), "f"(b)); return r;
}
__device__ __forceinline__ void fma2(ull& d, ull a, ull b) {
    asm("fma.rn.f32x2 %0, %1, %2, %3;" : "=l"(d) : "l"(a), "l"(b), "l"(d));
}
__device__ __forceinline__ float2 upk(ull v) {
    float2 r; asm("mov.b64 {%0, %1}, %2;" : "=f"(r.x), "=f"(r.y) : "l"(v)); return r;
}

// ---------------- scratch ----------------
// xraw / xc / zs / delta / y are CHANNEL-MAJOR: [(b*DI + d) * LSEQ + l]
__device__ float g_Wu[DM * DMO];
__device__ float g_bu[DM];
__device__ float g_xn[TOK * DMO];
__device__ float g_u[TOK * DM];
__device__ float g_xraw[NCH * LSEQ];
__device__ float g_xc[NCH * LSEQ];
__device__ float g_zs[NCH * LSEQ];
__device__ float g_delta[NCH * LSEQ];
__device__ float g_Bm[TOK * DS];
__device__ float g_Cm[TOK * DS];
__device__ float g_y[NCH * LSEQ];
__device__ float g_m[TOK * DM];
__device__ float g_P[NUNIT * DS];
__device__ float g_q[NUNIT * DS];
__device__ float g_hin[NUNIT * DS];

// ---------------- K0: compose W_u = W_fp @ W_ip, b_u = W_fp@b_ip + b_fp ----------
__global__ void k_combine(const float* __restrict__ Wfp, const float* __restrict__ Wip,
                          const float* __restrict__ bip, const float* __restrict__ bfp) {
    int idx = blockIdx.x * 256 + threadIdx.x;
    int o = idx / DMO, i = idx % DMO;
    float s = 0.f;
    for (int k = 0; k < DM; ++k) s = fmaf(Wfp[o * DM + k], Wip[k * DMO + i], s);
    g_Wu[idx] = s;
    if (blockIdx.x == 0 && threadIdx.x < DM) {
        int t = threadIdx.x;
        float sb = bfp[t];
        for (int k = 0; k < DM; ++k) sb = fmaf(Wfp[t * DM + k], bip[k], sb);
        g_bu[t] = sb;
    }
}

// ---------------- K1: rmsnorm1 + u = W_u @ xn + b_u ------------------------------
// sx [i][t] 64x68 (transposed), swT [i][o] 64x132, f32x2 GEMM
__global__ void k_rms_u(const float* __restrict__ x, const float* __restrict__ wn1) {
    extern __shared__ float sm[];
    float* sx  = sm;                 // 64*68
    float* swT = sm + 64 * 68;       // 64*132
    float* ssc = swT + 64 * 132;     // 64
    int tid = threadIdx.x;
    long t0 = (long)blockIdx.x * 64;

    for (int idx = tid; idx < 64 * 64; idx += 256) {
        int i = idx & 63, t = idx >> 6;
        sx[i * 68 + t] = x[(t0 + t) * DMO + i];
    }
    for (int idx = tid; idx < DM * DMO; idx += 256) {
        int i = idx & 63, o = idx >> 6;
        swT[i * 132 + o] = g_Wu[o * DMO + i];
    }
    __syncthreads();
    if (tid < 64) {
        float ss = 0.f;
        for (int i = 0; i < DMO; ++i) { float v = sx[i * 68 + tid]; ss = fmaf(v, v, ss); }
        ssc[tid] = rsqrtf(ss * (1.f / DMO) + 1e-5f);
    }
    __syncthreads();
    for (int idx = tid; idx < 64 * 64; idx += 256) {
        int i = idx & 63, t = idx >> 6;
        float v = sx[i * 68 + t] * ssc[t] * wn1[i];
        sx[i * 68 + t] = v;
        g_xn[(t0 + t) * DMO + i] = v;
    }
    __syncthreads();
    int tx = tid & 31, ty = tid >> 5;
    ull acc[4][4] = {};
    for (int i = 0; i < DMO; ++i) {
        float4 w4 = *(const float4*)&swT[i * 132 + (tx << 2)];
        ull wd0 = pk2(w4.x, w4.x), wd1 = pk2(w4.y, w4.y);
        ull wd2 = pk2(w4.z, w4.z), wd3 = pk2(w4.w, w4.w);
        ulonglong2 xa = *(const ulonglong2*)&sx[i * 68 + ty * 8];
        ulonglong2 xb = *(const ulonglong2*)&sx[i * 68 + ty * 8 + 4];
        fma2(acc[0][0], xa.x, wd0); fma2(acc[0][1], xa.x, wd1); fma2(acc[0][2], xa.x, wd2); fma2(acc[0][3], xa.x, wd3);
        fma2(acc[1][0], xa.y, wd0); fma2(acc[1][1], xa.y, wd1); fma2(acc[1][2], xa.y, wd2); fma2(acc[1][3], xa.y, wd3);
        fma2(acc[2][0], xb.x, wd0); fma2(acc[2][1], xb.x, wd1); fma2(acc[2][2], xb.x, wd2); fma2(acc[2][3], xb.x, wd3);
        fma2(acc[3][0], xb.y, wd0); fma2(acc[3][1], xb.y, wd1); fma2(acc[3][2], xb.y, wd2); fma2(acc[3][3], xb.y, wd3);
    }
    float4 bq = *(const float4*)&g_bu[tx << 2];
    #pragma unroll
    for (int p = 0; p < 4; ++p) {
        float2 v0 = upk(acc[p][0]), v1 = upk(acc[p][1]), v2 = upk(acc[p][2]), v3 = upk(acc[p][3]);
        long ta = t0 + ty * 8 + 2 * p, tb = ta + 1;
        float4 lo = make_float4(v0.x + bq.x, v1.x + bq.y, v2.x + bq.z, v3.x + bq.w);
        float4 hi = make_float4(v0.y + bq.x, v1.y + bq.y, v2.y + bq.z, v3.y + bq.w);
        *(float4*)&g_u[ta * DM + (tx << 2)] = lo;
        *(float4*)&g_u[tb * DM + (tx << 2)] = hi;
    }
}

// ---------------- K2: xz = in_proj @ u ; xraw / silu(z), channel-major out --------
__global__ void k_inproj(const float* __restrict__ Win) {
    extern __shared__ float sm[];
    float* su  = sm;              // [i][t] 128*68
    float* swT = sm + 128 * 68;   // [i][e] 128*132; reused as stage [e][t] 128*65
    int tid = threadIdx.x;
    long t0 = (long)blockIdx.x * 64;
    int e0 = blockIdx.y * 128;
    int b = (int)(t0 >> 12);
    int l0 = (int)(t0 & (LSEQ - 1));

    for (int idx = tid; idx < 64 * DM; idx += 256) {
        int i = idx & 127, t = idx >> 7;
        su[i * 68 + t] = g_u[(t0 + t) * DM + i];
    }
    for (int idx = tid; idx < 128 * DM; idx += 256) {
        int i = idx & 127, e = idx >> 7;
        swT[i * 132 + e] = Win[(long)(e0 + e) * DM + i];
    }
    __syncthreads();
    int tx = tid & 31, ty = tid >> 5;
    ull acc[4][4] = {};
    for (int i = 0; i < DM; ++i) {
        float4 w4 = *(const float4*)&swT[i * 132 + (tx << 2)];
        ull wd0 = pk2(w4.x, w4.x), wd1 = pk2(w4.y, w4.y);
        ull wd2 = pk2(w4.z, w4.z), wd3 = pk2(w4.w, w4.w);
        ulonglong2 xa = *(const ulonglong2*)&su[i * 68 + ty * 8];
        ulonglong2 xb = *(const ulonglong2*)&su[i * 68 + ty * 8 + 4];
        fma2(acc[0][0], xa.x, wd0); fma2(acc[0][1], xa.x, wd1); fma2(acc[0][2], xa.x, wd2); fma2(acc[0][3], xa.x, wd3);
        fma2(acc[1][0], xa.y, wd0); fma2(acc[1][1], xa.y, wd1); fma2(acc[1][2], xa.y, wd2); fma2(acc[1][3], xa.y, wd3);
        fma2(acc[2][0], xb.x, wd0); fma2(acc[2][1], xb.x, wd1); fma2(acc[2][2], xb.x, wd2); fma2(acc[2][3], xb.x, wd3);
        fma2(acc[3][0], xb.y, wd0); fma2(acc[3][1], xb.y, wd1); fma2(acc[3][2], xb.y, wd2); fma2(acc[3][3], xb.y, wd3);
    }
    __syncthreads();   // swT dead -> stage [e][t]
    float* stage = swT;
    #pragma unroll
    for (int p = 0; p < 4; ++p)
        #pragma unroll
        for (int j = 0; j < 4; ++j) {
            float2 v = upk(acc[p][j]);
            int e = (tx << 2) + j, t = ty * 8 + 2 * p;
            stage[e * 65 + t] = v.x;
            stage[e * 65 + t + 1] = v.y;
        }
    __syncthreads();
    bool isz = (e0 >= DI);
    float* dst = isz ? g_zs : g_xraw;
    int dbase = isz ? (e0 - DI) : e0;
    for (int idx = tid; idx < 128 * 64; idx += 256) {
        int e = idx >> 6, t = idx & 63;
        float v = stage[e * 65 + t];
        if (isz) v = v / (1.f + __expf(-v));
        dst[(long)(b * DI + dbase + e) * LSEQ + l0 + t] = v;
    }
}

// ---------------- K3: causal depthwise conv (k=4) + bias + silu ------------------
__global__ void k_conv(const float* __restrict__ cw, const float* __restrict__ cb) {
    int ch = blockIdx.x;
    int d = ch & (DI - 1);
    const float* src = g_xraw + (long)ch * LSEQ;
    float* dst = g_xc + (long)ch * LSEQ;
    float w0 = cw[d * 4 + 0], w1 = cw[d * 4 + 1], w2 = cw[d * 4 + 2], w3 = cw[d * 4 + 3];
    float bb = cb[d];
    for (int l = threadIdx.x; l < LSEQ; l += 256) {
        float acc = bb;
        acc = fmaf(w3, src[l], acc);
        if (l >= 1) acc = fmaf(w2, src[l - 1], acc);
        if (l >= 2) acc = fmaf(w1, src[l - 2], acc);
        if (l >= 3) acc = fmaf(w0, src[l - 3], acc);
        dst[l] = acc / (1.f + __expf(-acc));
    }
}

// ---------------- K4: x_dbl = x_proj @ x ; B,C split ; delta = softplus(...) -----
__global__ void k_xproj(const float* __restrict__ Xp, const float* __restrict__ Wdt,
                        const float* __restrict__ bdt) {
    extern __shared__ float sm[];
    float* sx   = sm;                    // phase1: [t][k] 64*260 ; phase2: sdel [d][t] 256*65
    float* spTT = sm + 16640;            // [e][k] 40*260
    float* sdbl = spTT + 40 * 260;       // 64*40
    int tid = threadIdx.x;
    long t0 = (long)blockIdx.x * 64;
    int b = (int)(t0 >> 12);
    int l0 = (int)(t0 & (LSEQ - 1));

    for (int idx = tid; idx < 64 * DI; idx += 256) {
        int t = idx & 63, d = idx >> 6;
        sx[t * 260 + d] = g_xc[(long)(b * DI + d) * LSEQ + l0 + t];
    }
    for (int idx = tid; idx < 40 * DI; idx += 256) {
        int k = idx & 255, e = idx >> 8;
        spTT[e * 260 + k] = Xp[e * DI + k];
    }
    __syncthreads();
    {
        int t = tid >> 2, eb = (tid & 3) * 10;
        float acc[10] = {};
        for (int k = 0; k < DI; k += 4) {
            float4 xv = *(const float4*)&sx[t * 260 + k];
            #pragma unroll
            for (int e = 0; e < 10; ++e) {
                float4 wv = *(const float4*)&spTT[(eb + e) * 260 + k];
                acc[e] = fmaf(xv.x, wv.x, fmaf(xv.y, wv.y, fmaf(xv.z, wv.z, fmaf(xv.w, wv.w, acc[e]))));
            }
        }
        #pragma unroll
        for (int e = 0; e < 10; ++e) sdbl[t * 40 + eb + e] = acc[e];
    }
    __syncthreads();
    for (int idx = tid; idx < 64 * DS; idx += 256) {
        int t = idx >> 4, s = idx & 15;
        g_Bm[(t0 + t) * DS + s] = sdbl[t * 40 + 8 + s];
        g_Cm[(t0 + t) * DS + s] = sdbl[t * 40 + 24 + s];
    }
    {
        int d = tid;
        float wr[8];
        #pragma unroll
        for (int r = 0; r < 8; ++r) wr[r] = Wdt[d * 8 + r];
        float bb = bdt[d];
        for (int t = 0; t < 64; ++t) {
            float pre = bb;
            #pragma unroll
            for (int r = 0; r < 8; ++r) pre = fmaf(sdbl[t * 40 + r], wr[r], pre);
            float sp = (pre > 20.f) ? pre : log1pf(__expf(pre));
            sx[d * 65 + t] = sp;
        }
    }
    __syncthreads();
    for (int idx = tid; idx < DI * 64; idx += 256) {
        int d = idx >> 6, t = idx & 63;
        g_delta[(long)(b * DI + d) * LSEQ + l0 + t] = sx[d * 65 + t];
    }
}

// ---------------- K5a: per-chunk decay product P and local state q ----------------
__global__ void k_scan1(const float* __restrict__ Alog) {
    int u = threadIdx.x >> 4;
    int s = threadIdx.x & 15;
    int unit = blockIdx.x * 16 + u;
    int g = unit & (NG - 1);
    int ch = unit >> 6;
    int b = ch >> 8, d = ch & 255;
    float Aval = -__expf(Alog[d * DS + s]);
    const float* pd = g_delta + (long)ch * LSEQ + g * CHK;
    const float* px = g_xc    + (long)ch * LSEQ + g * CHK;
    const float* pB = g_Bm    + ((long)b * LSEQ + g * CHK) * DS + s;
    float P = 1.f, q = 0.f;
    #pragma unroll 8
    for (int t = 0; t < CHK; ++t) {
        float dv = pd[t];
        float xv = px[t];
        float Bv = pB[t * DS];
        float a = __expf(dv * Aval);
        P *= a;
        q = fmaf(a, q, dv * xv * Bv);
    }
    long idx = (long)unit * DS + s;
    g_P[idx] = P;
    g_q[idx] = q;
}

// ---------------- K5b: propagate h_in across chunks ------------------------------
__global__ void k_scan2() {
    int tid = blockIdx.x * 256 + threadIdx.x;
    int ch = tid >> 4, s = tid & 15;
    float h = 0.f;
    long base = (long)ch * NG * DS + s;
    #pragma unroll 8
    for (int g = 0; g < NG; ++g) {
        long idx = base + (long)g * DS;
        g_hin[idx] = h;
        h = fmaf(g_P[idx], h, g_q[idx]);
    }
}

// ---------------- K5c: local scan from h_in, y = (C.h + x*D) * silu(z) -----------
__global__ void k_scan3(const float* __restrict__ Alog, const float* __restrict__ Dp_) {
    __shared__ float ybuf[16 * CHK];
    int u = threadIdx.x >> 4;
    int s = threadIdx.x & 15;
    int unit = blockIdx.x * 16 + u;
    int g = unit & (NG - 1);
    int ch = unit >> 6;
    int b = ch >> 8, d = ch & 255;
    float Aval = -__expf(Alog[d * DS + s]);
    float Dp = Dp_[d];
    const float* pd = g_delta + (long)ch * LSEQ + g * CHK;
    const float* px = g_xc    + (long)ch * LSEQ + g * CHK;
    const float* pz = g_zs    + (long)ch * LSEQ + g * CHK;
    const float* pB = g_Bm    + ((long)b * LSEQ + g * CHK) * DS + s;
    const float* pC = g_Cm    + ((long)b * LSEQ + g * CHK) * DS + s;
    float h = g_hin[(long)unit * DS + s];
    #pragma unroll 4
    for (int t = 0; t < CHK; ++t) {
        float dv = pd[t];
        float xv = px[t];
        float Bv = pB[t * DS];
        float Cv = pC[t * DS];
        float a = __expf(dv * Aval);
        h = fmaf(a, h, dv * xv * Bv);
        float p = h * Cv;
        p += __shfl_xor_sync(0xffffffffu, p, 8);
        p += __shfl_xor_sync(0xffffffffu, p, 4);
        p += __shfl_xor_sync(0xffffffffu, p, 2);
        p += __shfl_xor_sync(0xffffffffu, p, 1);
        if (s == 0) ybuf[u * CHK + t] = (p + xv * Dp) * pz[t];
    }
    __syncthreads();
    float* py = g_y + (long)ch * LSEQ + (long)(blockIdx.x & 3) * 1024;
    for (int i = threadIdx.x; i < 16 * CHK; i += 256) py[i] = ybuf[i];
}

// ---------------- K6: m = rmsnorm2(mamba_out @ y) + u -----------------------------
// syT [k][t] 256x68, swT [k][o] 256x132, f32x2 GEMM
__global__ void k_outproj(const float* __restrict__ Wmo, const float* __restrict__ wn2) {
    extern __shared__ float sm[];
    float* syT = sm;               // 256*68
    float* swT = sm + 256 * 68;    // 256*132
    int tid = threadIdx.x;
    long t0 = (long)blockIdx.x * 64;
    int b = (int)(t0 >> 12);
    int lpos = (int)(t0 & (LSEQ - 1));

    for (int idx = tid; idx < DI * 64; idx += 256) {
        int t = idx & 63, k = idx >> 6;
        syT[k * 68 + t] = g_y[(long)(b * DI + k) * LSEQ + lpos + t];
    }
    for (int idx = tid; idx < DM * DI; idx += 256) {
        int k = idx & 255, o = idx >> 8;
        swT[k * 132 + o] = Wmo[o * DI + k];
    }
    __syncthreads();
    int tx = tid & 31, ty = tid >> 5;
    ull acc[4][4] = {};
    for (int k = 0; k < DI; ++k) {
        float4 w4 = *(const float4*)&swT[k * 132 + (tx << 2)];
        ull wd0 = pk2(w4.x, w4.x), wd1 = pk2(w4.y, w4.y);
        ull wd2 = pk2(w4.z, w4.z), wd3 = pk2(w4.w, w4.w);
        ulonglong2 xa = *(const ulonglong2*)&syT[k * 68 + ty * 8];
        ulonglong2 xb = *(const ulonglong2*)&syT[k * 68 + ty * 8 + 4];
        fma2(acc[0][0], xa.x, wd0); fma2(acc[0][1], xa.x, wd1); fma2(acc[0][2], xa.x, wd2); fma2(acc[0][3], xa.x, wd3);
        fma2(acc[1][0], xa.y, wd0); fma2(acc[1][1], xa.y, wd1); fma2(acc[1][2], xa.y, wd2); fma2(acc[1][3], xa.y, wd3);
        fma2(acc[2][0], xb.x, wd0); fma2(acc[2][1], xb.x, wd1); fma2(acc[2][2], xb.x, wd2); fma2(acc[2][3], xb.x, wd3);
        fma2(acc[3][0], xb.y, wd0); fma2(acc[3][1], xb.y, wd1); fma2(acc[3][2], xb.y, wd2); fma2(acc[3][3], xb.y, wd3);
    }
    float af[8][4];
    #pragma unroll
    for (int p = 0; p < 4; ++p)
        #pragma unroll
        for (int j = 0; j < 4; ++j) {
            float2 v = upk(acc[p][j]);
            af[2 * p][j] = v.x;
            af[2 * p + 1][j] = v.y;
        }
    float4 w2q = *(const float4*)&wn2[tx << 2];
    #pragma unroll
    for (int r = 0; r < 8; ++r) {
        float ss = 0.f;
        #pragma unroll
        for (int j = 0; j < 4; ++j) ss = fmaf(af[r][j], af[r][j], ss);
        #pragma unroll
        for (int off = 16; off >= 1; off >>= 1) ss += __shfl_xor_sync(0xffffffffu, ss, off);
        float sc = rsqrtf(ss * (1.f / DM) + 1e-5f);
        long t = t0 + ty * 8 + r;
        float4 uq = *(const float4*)&g_u[t * DM + (tx << 2)];
        float4 ov = make_float4(af[r][0] * sc * w2q.x + uq.x,
                                af[r][1] * sc * w2q.y + uq.y,
                                af[r][2] * sc * w2q.z + uq.z,
                                af[r][3] * sc * w2q.w + uq.w);
        *(float4*)&g_m[t * DM + (tx << 2)] = ov;
    }
}

// ---------------- K7: w = swish(W_wp@xn+b) ; out = W_op@(w*m)+b + x ---------------
__global__ void k_final(const float* __restrict__ Wwp, const float* __restrict__ bwp,
                        const float* __restrict__ Wop, const float* __restrict__ bop,
                        const float* __restrict__ x, float* __restrict__ out) {
    extern __shared__ float sm[];
    float* sxn  = sm;                      // [i][t] 64*68
    float* smm  = sxn + 64 * 68;           // [t][c] 64*132
    float* swpT = smm + 64 * 132;          // [i][c] 64*132
    float* sopT = swpT + 64 * 132;         // [c][o] 128*68
    int tid = threadIdx.x;
    long t0 = (long)blockIdx.x * 64;

    for (int idx = tid; idx < 64 * DM; idx += 256) {
        int c = idx & 127, t = idx >> 7;
        smm[t * 132 + c] = g_m[(t0 + t) * DM + c];
    }
    for (int idx = tid; idx < 64 * 64; idx += 256) {
        int i = idx & 63, t = idx >> 6;
        sxn[i * 68 + t] = g_xn[(t0 + t) * DMO + i];
    }
    for (int idx = tid; idx < DM * DMO; idx += 256) {
        int i = idx & 63, c = idx >> 6;
        swpT[i * 132 + c] = Wwp[c * DMO + i];
    }
    for (int idx = tid; idx < DMO * DM; idx += 256) {
        int c = idx & 127, o = idx >> 7;
        sopT[c * 68 + o] = Wop[o * DM + c];
    }
    __syncthreads();
    int tx = tid & 31, ty = tid >> 5;
    {
        ull acc[4][4] = {};
        for (int i = 0; i < DMO; ++i) {
            float4 w4 = *(const float4*)&swpT[i * 132 + (tx << 2)];
            ull wd0 = pk2(w4.x, w4.x), wd1 = pk2(w4.y, w4.y);
            ull wd2 = pk2(w4.z, w4.z), wd3 = pk2(w4.w, w4.w);
            ulonglong2 xa = *(const ulonglong2*)&sxn[i * 68 + ty * 8];
            ulonglong2 xb = *(const ulonglong2*)&sxn[i * 68 + ty * 8 + 4];
            fma2(acc[0][0], xa.x, wd0); fma2(acc[0][1], xa.x, wd1); fma2(acc[0][2], xa.x, wd2); fma2(acc[0][3], xa.x, wd3);
            fma2(acc[1][0], xa.y, wd0); fma2(acc[1][1], xa.y, wd1); fma2(acc[1][2], xa.y, wd2); fma2(acc[1][3], xa.y, wd3);
            fma2(acc[2][0], xb.x, wd0); fma2(acc[2][1], xb.x, wd1); fma2(acc[2][2], xb.x, wd2); fma2(acc[2][3], xb.x, wd3);
            fma2(acc[3][0], xb.y, wd0); fma2(acc[3][1], xb.y, wd1); fma2(acc[3][2], xb.y, wd2); fma2(acc[3][3], xb.y, wd3);
        }
        float4 bq = *(const float4*)&bwp[tx << 2];
        float bj[4] = {bq.x, bq.y, bq.z, bq.w};
        #pragma unroll
        for (int p = 0; p < 4; ++p)
            #pragma unroll
            for (int j = 0; j < 4; ++j) {
                float2 v = upk(acc[p][j]);
                int c = (tx << 2) + j;
                int ta = ty * 8 + 2 * p;
                float va = v.x + bj[j], vb = v.y + bj[j];
                float wa = va / (1.f + __expf(-va));
                float wb = vb / (1.f + __expf(-vb));
                smm[ta * 132 + c] *= wa;
                smm[(ta + 1) * 132 + c] *= wb;
            }
    }
    __syncthreads();
    {
        int rowg = tid >> 4;           // 16 groups x 4 rows
        int o4 = (tid & 15) << 2;
        float a2[4][4] = {};
        for (int c = 0; c < DM; c += 4) {
            float4 q0 = *(const float4*)&sopT[(c + 0) * 68 + o4];
            float4 q1 = *(const float4*)&sopT[(c + 1) * 68 + o4];
            float4 q2 = *(const float4*)&sopT[(c + 2) * 68 + o4];
            float4 q3 = *(const float4*)&sopT[(c + 3) * 68 + o4];
            #pragma unroll
            for (int rr = 0; rr < 4; ++rr) {
                float4 pv = *(const float4*)&smm[(rowg * 4 + rr) * 132 + c];
                a2[rr][0] = fmaf(pv.x, q0.x, fmaf(pv.y, q1.x, fmaf(pv.z, q2.x, fmaf(pv.w, q3.x, a2[rr][0]))));
                a2[rr][1] = fmaf(pv.x, q0.y, fmaf(pv.y, q1.y, fmaf(pv.z, q2.y, fmaf(pv.w, q3.y, a2[rr][1]))));
                a2[rr][2] = fmaf(pv.x, q0.z, fmaf(pv.y, q1.z, fmaf(pv.z, q2.z, fmaf(pv.w, q3.z, a2[rr][2]))));
                a2[rr][3] = fmaf(pv.x, q0.w, fmaf(pv.y, q1.w, fmaf(pv.z, q2.w, fmaf(pv.w, q3.w, a2[rr][3]))));
            }
        }
        float4 bq = *(const float4*)&bop[o4];
        #pragma unroll
        for (int rr = 0; rr < 4; ++rr) {
            long tg = t0 + rowg * 4 + rr;
            float4 xq = *(const float4*)&x[tg * DMO + o4];
            float4 ov = make_float4(a2[rr][0] + bq.x + xq.x, a2[rr][1] + bq.y + xq.y,
                                    a2[rr][2] + bq.z + xq.z, a2[rr][3] + bq.w + xq.w);
            *(float4*)&out[tg * DMO + o4] = ov;
        }
    }
}

// ---------------- launch -----------------------------------------------------------
extern "C" void kernel_launch(void* const* d_in, const int* in_sizes, int n_in,
                              void* d_out, int out_size) {
    const float* x    = (const float*)d_in[0];
    const float* wn1  = (const float*)d_in[1];
    const float* wn2  = (const float*)d_in[2];
    const float* Wip  = (const float*)d_in[3];
    const float* bip  = (const float*)d_in[4];
    const float* Wfp  = (const float*)d_in[5];
    const float* bfp  = (const float*)d_in[6];
    const float* Wwp  = (const float*)d_in[7];
    const float* bwp  = (const float*)d_in[8];
    const float* Wop  = (const float*)d_in[9];
    const float* bop  = (const float*)d_in[10];
    const float* Win  = (const float*)d_in[11];
    const float* cw   = (const float*)d_in[12];
    const float* cb   = (const float*)d_in[13];
    const float* Xp   = (const float*)d_in[14];
    const float* Wdt  = (const float*)d_in[15];
    const float* bdt  = (const float*)d_in[16];
    const float* Alog = (const float*)d_in[17];
    const float* Dpar = (const float*)d_in[18];
    const float* Wmo  = (const float*)d_in[19];
    float* out = (float*)d_out;

    const int SM_K1 = (64 * 68 + 64 * 132 + 64) * 4;
    const int SM_K2 = (128 * 68 + 128 * 132) * 4;
    const int SM_K4 = (16640 + 40 * 260 + 64 * 40) * 4;
    const int SM_K6 = (256 * 68 + 256 * 132) * 4;
    const int SM_K7 = (64 * 68 + 64 * 132 + 64 * 132 + 128 * 68) * 4;

    cudaFuncSetAttribute(k_rms_u,   cudaFuncAttributeMaxDynamicSharedMemorySize, SM_K1);
    cudaFuncSetAttribute(k_inproj,  cudaFuncAttributeMaxDynamicSharedMemorySize, SM_K2);
    cudaFuncSetAttribute(k_xproj,   cudaFuncAttributeMaxDynamicSharedMemorySize, SM_K4);
    cudaFuncSetAttribute(k_outproj, cudaFuncAttributeMaxDynamicSharedMemorySize, SM_K6);
    cudaFuncSetAttribute(k_final,   cudaFuncAttributeMaxDynamicSharedMemorySize, SM_K7);

    k_combine<<<32, 256>>>(Wfp, Wip, bip, bfp);
    k_rms_u<<<TOK / 64, 256, SM_K1>>>(x, wn1);
    k_inproj<<<dim3(TOK / 64, 4), 256, SM_K2>>>(Win);
    k_conv<<<NCH, 256>>>(cw, cb);
    k_xproj<<<TOK / 64, 256, SM_K4>>>(Xp, Wdt, bdt);
    k_scan1<<<NUNIT / 16, 256>>>(Alog);
    k_scan2<<<64, 256>>>();
    k_scan3<<<NUNIT / 16, 256>>>(Alog, Dpar);
    k_outproj<<<TOK / 64, 256, SM_K6>>>(Wmo, wn2);
    k_final<<<TOK / 64, 256, SM_K7>>>(Wwp, bwp, Wop, bop, x, out);
}

// round 6
// speedup vs baseline: 1.4867x; 1.4867x over previous
#include <cuda_runtime.h>

#define TOK 16384
#define LSEQ 4096
#define NB 4
#define DMO 64      // input/output dim D
#define DM 128      // d_model of mamba (2D)
#define DI 256      // d_inner
#define DS 16       // d_state
#define DTR 8       // dt_rank
#define NCH 1024    // NB * DI channels
#define CHK 64      // chunk length
#define NG (LSEQ / CHK)   // 64 chunks
#define NUNIT (NCH * NG)  // 65536 units

typedef unsigned long long ull;

__device__ __forceinline__ ull pk2(float a, float b) {
    ull r; asm("mov.b64 %0, {%1, %2};" : "=l"(r) : "f"(a), "f"(b)); return r;
}
__device__ __forceinline__ void fma2(ull& d, ull a, ull b) {
    asm("fma.rn.f32x2 %0, %1, %2, %3;" : "=l"(d) : "l"(a), "l"(b), "l"(d));
}
__device__ __forceinline__ float2 upk(ull v) {
    float2 r; asm("mov.b64 {%0, %1}, %2;" : "=f"(r.x), "=f"(r.y) : "l"(v)); return r;
}

// ---------------- scratch ----------------
// xc / zs / delta / y are CHANNEL-MAJOR: [(b*DI + d) * LSEQ + l]
__device__ float g_Wu[DM * DMO];      // W_fp @ W_ip
__device__ float g_bu[DM];            // W_fp @ b_ip + b_fp
__device__ float g_Wc[2 * DI * DMO];  // in_proj @ W_u   (512 x 64)
__device__ float g_bc[2 * DI];        // in_proj @ b_u
__device__ float g_xn[TOK * DMO];
__device__ float g_u[TOK * DM];
__device__ float g_xc[NCH * LSEQ];
__device__ float g_zs[NCH * LSEQ];
__device__ float g_delta[NCH * LSEQ];
__device__ float g_Bm[TOK * DS];
__device__ float g_Cm[TOK * DS];
__device__ float g_y[NCH * LSEQ];
__device__ float g_m[TOK * DM];
__device__ float g_P[NUNIT * DS];
__device__ float g_q[NUNIT * DS];
__device__ float g_hin[NUNIT * DS];

// ---------------- K0: compose W_u = W_fp @ W_ip, b_u = W_fp@b_ip + b_fp ----------
__global__ void k_combine(const float* __restrict__ Wfp, const float* __restrict__ Wip,
                          const float* __restrict__ bip, const float* __restrict__ bfp) {
    int idx = blockIdx.x * 256 + threadIdx.x;
    int o = idx / DMO, i = idx % DMO;
    float s = 0.f;
    for (int k = 0; k < DM; ++k) s = fmaf(Wfp[o * DM + k], Wip[k * DMO + i], s);
    g_Wu[idx] = s;
    if (blockIdx.x == 0 && threadIdx.x < DM) {
        int t = threadIdx.x;
        float sb = bfp[t];
        for (int k = 0; k < DM; ++k) sb = fmaf(Wfp[t * DM + k], bip[k], sb);
        g_bu[t] = sb;
    }
}

// ---------------- K0b: compose W_c = in_proj @ W_u, b_c = in_proj @ b_u ----------
__global__ void k_combine2(const float* __restrict__ Win) {
    int idx = blockIdx.x * 256 + threadIdx.x;   // 128 blocks -> 32768 = 512*64
    int e = idx >> 6, i = idx & 63;
    float s = 0.f;
    for (int k = 0; k < DM; ++k) s = fmaf(Win[(long)e * DM + k], g_Wu[k * DMO + i], s);
    g_Wc[idx] = s;
    if (i == 0) {
        float sb = 0.f;
        for (int k = 0; k < DM; ++k) sb = fmaf(Win[(long)e * DM + k], g_bu[k], sb);
        g_bc[e] = sb;
    }
}

// ---------------- K1: rmsnorm1 + u = W_u @ xn + b_u ------------------------------
__global__ void k_rms_u(const float* __restrict__ x, const float* __restrict__ wn1) {
    extern __shared__ float sm[];
    float* sx  = sm;                 // 64*68 [i][t]
    float* swT = sm + 64 * 68;       // 64*132 [i][o]
    float* ssc = swT + 64 * 132;     // 64
    int tid = threadIdx.x;
    long t0 = (long)blockIdx.x * 64;

    for (int idx = tid; idx < 64 * 64; idx += 256) {
        int i = idx & 63, t = idx >> 6;
        sx[i * 68 + t] = x[(t0 + t) * DMO + i];
    }
    for (int idx = tid; idx < DM * DMO; idx += 256) {
        int i = idx & 63, o = idx >> 6;
        swT[i * 132 + o] = g_Wu[o * DMO + i];
    }
    __syncthreads();
    if (tid < 64) {
        float ss = 0.f;
        for (int i = 0; i < DMO; ++i) { float v = sx[i * 68 + tid]; ss = fmaf(v, v, ss); }
        ssc[tid] = rsqrtf(ss * (1.f / DMO) + 1e-5f);
    }
    __syncthreads();
    for (int idx = tid; idx < 64 * 64; idx += 256) {
        int i = idx & 63, t = idx >> 6;
        float v = sx[i * 68 + t] * ssc[t] * wn1[i];
        sx[i * 68 + t] = v;
        g_xn[(t0 + t) * DMO + i] = v;
    }
    __syncthreads();
    int tx = tid & 31, ty = tid >> 5;
    ull acc[4][4] = {};
    for (int i = 0; i < DMO; ++i) {
        float4 w4 = *(const float4*)&swT[i * 132 + (tx << 2)];
        ull wd0 = pk2(w4.x, w4.x), wd1 = pk2(w4.y, w4.y);
        ull wd2 = pk2(w4.z, w4.z), wd3 = pk2(w4.w, w4.w);
        ulonglong2 xa = *(const ulonglong2*)&sx[i * 68 + ty * 8];
        ulonglong2 xb = *(const ulonglong2*)&sx[i * 68 + ty * 8 + 4];
        fma2(acc[0][0], xa.x, wd0); fma2(acc[0][1], xa.x, wd1); fma2(acc[0][2], xa.x, wd2); fma2(acc[0][3], xa.x, wd3);
        fma2(acc[1][0], xa.y, wd0); fma2(acc[1][1], xa.y, wd1); fma2(acc[1][2], xa.y, wd2); fma2(acc[1][3], xa.y, wd3);
        fma2(acc[2][0], xb.x, wd0); fma2(acc[2][1], xb.x, wd1); fma2(acc[2][2], xb.x, wd2); fma2(acc[2][3], xb.x, wd3);
        fma2(acc[3][0], xb.y, wd0); fma2(acc[3][1], xb.y, wd1); fma2(acc[3][2], xb.y, wd2); fma2(acc[3][3], xb.y, wd3);
    }
    float4 bq = *(const float4*)&g_bu[tx << 2];
    #pragma unroll
    for (int p = 0; p < 4; ++p) {
        float2 v0 = upk(acc[p][0]), v1 = upk(acc[p][1]), v2 = upk(acc[p][2]), v3 = upk(acc[p][3]);
        long ta = t0 + ty * 8 + 2 * p, tb = ta + 1;
        float4 lo = make_float4(v0.x + bq.x, v1.x + bq.y, v2.x + bq.z, v3.x + bq.w);
        float4 hi = make_float4(v0.y + bq.x, v1.y + bq.y, v2.y + bq.z, v3.y + bq.w);
        *(float4*)&g_u[ta * DM + (tx << 2)] = lo;
        *(float4*)&g_u[tb * DM + (tx << 2)] = hi;
    }
}

// ---------------- K2: xz = W_c @ xn + b_c ; fused conv+silu (x) / silu (z) --------
// x-side blocks (e0 < DI) also compute a 3-token halo and apply the causal
// depthwise conv in smem, writing g_xc directly. z-side blocks write silu -> g_zs.
__global__ void k_inproj(const float* __restrict__ cw, const float* __restrict__ cb) {
    extern __shared__ float sm[];
    float* sxn   = sm;                 // [i][t] 64*68 ; cols 0-63 main, 64-66 halo
    float* swT   = sm + 64 * 68;       // [i][e] 64*132
    float* stage = swT + 64 * 132;     // [e][t'] 128*68 ; t'=0..2 halo, 3..66 main
    float* sbc   = stage + 128 * 68;   // 128 biases
    int tid = threadIdx.x;
    long t0 = (long)blockIdx.x * 64;
    int e0 = blockIdx.y * 128;
    int b = (int)(t0 >> 12);
    int l0 = (int)(t0 & (LSEQ - 1));
    bool isx = (e0 < DI);

    for (int idx = tid; idx < 64 * 64; idx += 256) {
        int i = idx & 63, t = idx >> 6;
        sxn[i * 68 + t] = g_xn[(t0 + t) * DMO + i];
    }
    for (int idx = tid; idx < 128 * 64; idx += 256) {
        int i = idx & 63, e = idx >> 6;
        swT[i * 132 + e] = g_Wc[(long)(e0 + e) * DMO + i];
    }
    if (tid < 128) sbc[tid] = g_bc[e0 + tid];
    if (isx && tid < 192) {   // halo xn: tokens t0-3..t0-1
        int i = tid & 63, j = tid >> 6;
        sxn[i * 68 + 64 + j] = (l0 > 0) ? g_xn[(t0 - 3 + j) * DMO + i] : 0.f;
    }
    __syncthreads();
    int tx = tid & 31, ty = tid >> 5;
    ull acc[4][4] = {};
    for (int i = 0; i < 64; ++i) {
        float4 w4 = *(const float4*)&swT[i * 132 + (tx << 2)];
        ull wd0 = pk2(w4.x, w4.x), wd1 = pk2(w4.y, w4.y);
        ull wd2 = pk2(w4.z, w4.z), wd3 = pk2(w4.w, w4.w);
        ulonglong2 xa = *(const ulonglong2*)&sxn[i * 68 + ty * 8];
        ulonglong2 xb = *(const ulonglong2*)&sxn[i * 68 + ty * 8 + 4];
        fma2(acc[0][0], xa.x, wd0); fma2(acc[0][1], xa.x, wd1); fma2(acc[0][2], xa.x, wd2); fma2(acc[0][3], xa.x, wd3);
        fma2(acc[1][0], xa.y, wd0); fma2(acc[1][1], xa.y, wd1); fma2(acc[1][2], xa.y, wd2); fma2(acc[1][3], xa.y, wd3);
        fma2(acc[2][0], xb.x, wd0); fma2(acc[2][1], xb.x, wd1); fma2(acc[2][2], xb.x, wd2); fma2(acc[2][3], xb.x, wd3);
        fma2(acc[3][0], xb.y, wd0); fma2(acc[3][1], xb.y, wd1); fma2(acc[3][2], xb.y, wd2); fma2(acc[3][3], xb.y, wd3);
    }
    // main tokens -> stage cols 3..66 (with bias)
    #pragma unroll
    for (int p = 0; p < 4; ++p)
        #pragma unroll
        for (int j = 0; j < 4; ++j) {
            float2 v = upk(acc[p][j]);
            int e = (tx << 2) + j, t = ty * 8 + 2 * p;
            float bce = sbc[e];
            stage[e * 68 + 3 + t] = v.x + bce;
            stage[e * 68 + 4 + t] = v.y + bce;
        }
    // halo xz for x blocks -> stage cols 0..2
    if (isx) {
        for (int p = tid; p < 3 * 128; p += 256) {
            int j = p >> 7, e = p & 127;
            float a = 0.f;
            if (l0 > 0) {
                a = sbc[e];
                for (int i = 0; i < 64; ++i)
                    a = fmaf(sxn[i * 68 + 64 + j], swT[i * 132 + e], a);
            }
            stage[e * 68 + j] = a;
        }
    }
    __syncthreads();
    if (isx) {
        for (int idx = tid; idx < 128 * 64; idx += 256) {
            int t = idx & 63, e = idx >> 6;
            int d = e0 + e;
            const float* st = &stage[e * 68];
            float4 w = *(const float4*)&cw[d * 4];
            float a = cb[d];
            a = fmaf(w.x, st[t], a);
            a = fmaf(w.y, st[t + 1], a);
            a = fmaf(w.z, st[t + 2], a);
            a = fmaf(w.w, st[t + 3], a);
            a = a / (1.f + __expf(-a));
            g_xc[(long)(b * DI + d) * LSEQ + l0 + t] = a;
        }
    } else {
        for (int idx = tid; idx < 128 * 64; idx += 256) {
            int t = idx & 63, e = idx >> 6;
            float v = stage[e * 68 + 3 + t];
            v = v / (1.f + __expf(-v));
            g_zs[(long)(b * DI + (e0 - DI) + e) * LSEQ + l0 + t] = v;
        }
    }
}

// ---------------- K4: x_dbl = x_proj @ x ; B,C split ; delta = softplus(...) -----
__global__ void k_xproj(const float* __restrict__ Xp, const float* __restrict__ Wdt,
                        const float* __restrict__ bdt) {
    extern __shared__ float sm[];
    float* sx   = sm;                    // phase1: [t][k] 64*260 ; phase2: sdel [d][t] 256*65
    float* spTT = sm + 16640;            // [e][k] 40*260
    float* sdbl = spTT + 40 * 260;       // 64*40
    int tid = threadIdx.x;
    long t0 = (long)blockIdx.x * 64;
    int b = (int)(t0 >> 12);
    int l0 = (int)(t0 & (LSEQ - 1));

    for (int idx = tid; idx < 64 * DI; idx += 256) {
        int t = idx & 63, d = idx >> 6;
        sx[t * 260 + d] = g_xc[(long)(b * DI + d) * LSEQ + l0 + t];
    }
    for (int idx = tid; idx < 40 * DI; idx += 256) {
        int k = idx & 255, e = idx >> 8;
        spTT[e * 260 + k] = Xp[e * DI + k];
    }
    __syncthreads();
    {
        int t = tid >> 2, eb = (tid & 3) * 10;
        float acc[10] = {};
        for (int k = 0; k < DI; k += 4) {
            float4 xv = *(const float4*)&sx[t * 260 + k];
            #pragma unroll
            for (int e = 0; e < 10; ++e) {
                float4 wv = *(const float4*)&spTT[(eb + e) * 260 + k];
                acc[e] = fmaf(xv.x, wv.x, fmaf(xv.y, wv.y, fmaf(xv.z, wv.z, fmaf(xv.w, wv.w, acc[e]))));
            }
        }
        #pragma unroll
        for (int e = 0; e < 10; ++e) sdbl[t * 40 + eb + e] = acc[e];
    }
    __syncthreads();
    for (int idx = tid; idx < 64 * DS; idx += 256) {
        int t = idx >> 4, s = idx & 15;
        g_Bm[(t0 + t) * DS + s] = sdbl[t * 40 + 8 + s];
        g_Cm[(t0 + t) * DS + s] = sdbl[t * 40 + 24 + s];
    }
    {
        int d = tid;
        float wr[8];
        #pragma unroll
        for (int r = 0; r < 8; ++r) wr[r] = Wdt[d * 8 + r];
        float bb = bdt[d];
        for (int t = 0; t < 64; ++t) {
            float pre = bb;
            #pragma unroll
            for (int r = 0; r < 8; ++r) pre = fmaf(sdbl[t * 40 + r], wr[r], pre);
            float sp = (pre > 20.f) ? pre : log1pf(__expf(pre));
            sx[d * 65 + t] = sp;
        }
    }
    __syncthreads();
    for (int idx = tid; idx < DI * 64; idx += 256) {
        int d = idx >> 6, t = idx & 63;
        g_delta[(long)(b * DI + d) * LSEQ + l0 + t] = sx[d * 65 + t];
    }
}

// ---------------- K5a: per-chunk decay product P and local state q ----------------
__global__ void k_scan1(const float* __restrict__ Alog) {
    int u = threadIdx.x >> 4;
    int s = threadIdx.x & 15;
    int unit = blockIdx.x * 16 + u;
    int g = unit & (NG - 1);
    int ch = unit >> 6;
    int b = ch >> 8, d = ch & 255;
    float Aval = -__expf(Alog[d * DS + s]);
    const float* pd = g_delta + (long)ch * LSEQ + g * CHK;
    const float* px = g_xc    + (long)ch * LSEQ + g * CHK;
    const float* pB = g_Bm    + ((long)b * LSEQ + g * CHK) * DS + s;
    float P = 1.f, q = 0.f;
    #pragma unroll 8
    for (int t = 0; t < CHK; ++t) {
        float dv = pd[t];
        float xv = px[t];
        float Bv = pB[t * DS];
        float a = __expf(dv * Aval);
        P *= a;
        q = fmaf(a, q, dv * xv * Bv);
    }
    long idx = (long)unit * DS + s;
    g_P[idx] = P;
    g_q[idx] = q;
}

// ---------------- K5b: propagate h_in across chunks ------------------------------
__global__ void k_scan2() {
    int tid = blockIdx.x * 256 + threadIdx.x;
    int ch = tid >> 4, s = tid & 15;
    float h = 0.f;
    long base = (long)ch * NG * DS + s;
    #pragma unroll 8
    for (int g = 0; g < NG; ++g) {
        long idx = base + (long)g * DS;
        g_hin[idx] = h;
        h = fmaf(g_P[idx], h, g_q[idx]);
    }
}

// ---------------- K5c: local scan from h_in, y = (C.h + x*D) * silu(z) -----------
__global__ void k_scan3(const float* __restrict__ Alog, const float* __restrict__ Dp_) {
    __shared__ float ybuf[16 * CHK];
    int u = threadIdx.x >> 4;
    int s = threadIdx.x & 15;
    int unit = blockIdx.x * 16 + u;
    int g = unit & (NG - 1);
    int ch = unit >> 6;
    int b = ch >> 8, d = ch & 255;
    float Aval = -__expf(Alog[d * DS + s]);
    float Dp = Dp_[d];
    const float* pd = g_delta + (long)ch * LSEQ + g * CHK;
    const float* px = g_xc    + (long)ch * LSEQ + g * CHK;
    const float* pz = g_zs    + (long)ch * LSEQ + g * CHK;
    const float* pB = g_Bm    + ((long)b * LSEQ + g * CHK) * DS + s;
    const float* pC = g_Cm    + ((long)b * LSEQ + g * CHK) * DS + s;
    float h = g_hin[(long)unit * DS + s];
    #pragma unroll 4
    for (int t = 0; t < CHK; ++t) {
        float dv = pd[t];
        float xv = px[t];
        float Bv = pB[t * DS];
        float Cv = pC[t * DS];
        float a = __expf(dv * Aval);
        h = fmaf(a, h, dv * xv * Bv);
        float p = h * Cv;
        p += __shfl_xor_sync(0xffffffffu, p, 8);
        p += __shfl_xor_sync(0xffffffffu, p, 4);
        p += __shfl_xor_sync(0xffffffffu, p, 2);
        p += __shfl_xor_sync(0xffffffffu, p, 1);
        if (s == 0) ybuf[u * CHK + t] = (p + xv * Dp) * pz[t];
    }
    __syncthreads();
    float* py = g_y + (long)ch * LSEQ + (long)(blockIdx.x & 3) * 1024;
    for (int i = threadIdx.x; i < 16 * CHK; i += 256) py[i] = ybuf[i];
}

// ---------------- K6: m = rmsnorm2(mamba_out @ y) + u -----------------------------
__global__ void k_outproj(const float* __restrict__ Wmo, const float* __restrict__ wn2) {
    extern __shared__ float sm[];
    float* syT = sm;               // 256*68
    float* swT = sm + 256 * 68;    // 256*132
    int tid = threadIdx.x;
    long t0 = (long)blockIdx.x * 64;
    int b = (int)(t0 >> 12);
    int lpos = (int)(t0 & (LSEQ - 1));

    for (int idx = tid; idx < DI * 64; idx += 256) {
        int t = idx & 63, k = idx >> 6;
        syT[k * 68 + t] = g_y[(long)(b * DI + k) * LSEQ + lpos + t];
    }
    for (int idx = tid; idx < DM * DI; idx += 256) {
        int k = idx & 255, o = idx >> 8;
        swT[k * 132 + o] = Wmo[o * DI + k];
    }
    __syncthreads();
    int tx = tid & 31, ty = tid >> 5;
    ull acc[4][4] = {};
    for (int k = 0; k < DI; ++k) {
        float4 w4 = *(const float4*)&swT[k * 132 + (tx << 2)];
        ull wd0 = pk2(w4.x, w4.x), wd1 = pk2(w4.y, w4.y);
        ull wd2 = pk2(w4.z, w4.z), wd3 = pk2(w4.w, w4.w);
        ulonglong2 xa = *(const ulonglong2*)&syT[k * 68 + ty * 8];
        ulonglong2 xb = *(const ulonglong2*)&syT[k * 68 + ty * 8 + 4];
        fma2(acc[0][0], xa.x, wd0); fma2(acc[0][1], xa.x, wd1); fma2(acc[0][2], xa.x, wd2); fma2(acc[0][3], xa.x, wd3);
        fma2(acc[1][0], xa.y, wd0); fma2(acc[1][1], xa.y, wd1); fma2(acc[1][2], xa.y, wd2); fma2(acc[1][3], xa.y, wd3);
        fma2(acc[2][0], xb.x, wd0); fma2(acc[2][1], xb.x, wd1); fma2(acc[2][2], xb.x, wd2); fma2(acc[2][3], xb.x, wd3);
        fma2(acc[3][0], xb.y, wd0); fma2(acc[3][1], xb.y, wd1); fma2(acc[3][2], xb.y, wd2); fma2(acc[3][3], xb.y, wd3);
    }
    float af[8][4];
    #pragma unroll
    for (int p = 0; p < 4; ++p)
        #pragma unroll
        for (int j = 0; j < 4; ++j) {
            float2 v = upk(acc[p][j]);
            af[2 * p][j] = v.x;
            af[2 * p + 1][j] = v.y;
        }
    float4 w2q = *(const float4*)&wn2[tx << 2];
    #pragma unroll
    for (int r = 0; r < 8; ++r) {
        float ss = 0.f;
        #pragma unroll
        for (int j = 0; j < 4; ++j) ss = fmaf(af[r][j], af[r][j], ss);
        #pragma unroll
        for (int off = 16; off >= 1; off >>= 1) ss += __shfl_xor_sync(0xffffffffu, ss, off);
        float sc = rsqrtf(ss * (1.f / DM) + 1e-5f);
        long t = t0 + ty * 8 + r;
        float4 uq = *(const float4*)&g_u[t * DM + (tx << 2)];
        float4 ov = make_float4(af[r][0] * sc * w2q.x + uq.x,
                                af[r][1] * sc * w2q.y + uq.y,
                                af[r][2] * sc * w2q.z + uq.z,
                                af[r][3] * sc * w2q.w + uq.w);
        *(float4*)&g_m[t * DM + (tx << 2)] = ov;
    }
}

// ---------------- K7: w = swish(W_wp@xn+b) ; out = W_op@(w*m)+b + x ---------------
__global__ void k_final(const float* __restrict__ Wwp, const float* __restrict__ bwp,
                        const float* __restrict__ Wop, const float* __restrict__ bop,
                        const float* __restrict__ x, float* __restrict__ out) {
    extern __shared__ float sm[];
    float* sxn  = sm;                      // [i][t] 64*68
    float* smm  = sxn + 64 * 68;           // [t][c] 64*132
    float* swpT = smm + 64 * 132;          // [i][c] 64*132
    float* sopT = swpT + 64 * 132;         // [c][o] 128*68
    int tid = threadIdx.x;
    long t0 = (long)blockIdx.x * 64;

    for (int idx = tid; idx < 64 * DM; idx += 256) {
        int c = idx & 127, t = idx >> 7;
        smm[t * 132 + c] = g_m[(t0 + t) * DM + c];
    }
    for (int idx = tid; idx < 64 * 64; idx += 256) {
        int i = idx & 63, t = idx >> 6;
        sxn[i * 68 + t] = g_xn[(t0 + t) * DMO + i];
    }
    for (int idx = tid; idx < DM * DMO; idx += 256) {
        int i = idx & 63, c = idx >> 6;
        swpT[i * 132 + c] = Wwp[c * DMO + i];
    }
    for (int idx = tid; idx < DMO * DM; idx += 256) {
        int c = idx & 127, o = idx >> 7;
        sopT[c * 68 + o] = Wop[o * DM + c];
    }
    __syncthreads();
    int tx = tid & 31, ty = tid >> 5;
    {
        ull acc[4][4] = {};
        for (int i = 0; i < DMO; ++i) {
            float4 w4 = *(const float4*)&swpT[i * 132 + (tx << 2)];
            ull wd0 = pk2(w4.x, w4.x), wd1 = pk2(w4.y, w4.y);
            ull wd2 = pk2(w4.z, w4.z), wd3 = pk2(w4.w, w4.w);
            ulonglong2 xa = *(const ulonglong2*)&sxn[i * 68 + ty * 8];
            ulonglong2 xb = *(const ulonglong2*)&sxn[i * 68 + ty * 8 + 4];
            fma2(acc[0][0], xa.x, wd0); fma2(acc[0][1], xa.x, wd1); fma2(acc[0][2], xa.x, wd2); fma2(acc[0][3], xa.x, wd3);
            fma2(acc[1][0], xa.y, wd0); fma2(acc[1][1], xa.y, wd1); fma2(acc[1][2], xa.y, wd2); fma2(acc[1][3], xa.y, wd3);
            fma2(acc[2][0], xb.x, wd0); fma2(acc[2][1], xb.x, wd1); fma2(acc[2][2], xb.x, wd2); fma2(acc[2][3], xb.x, wd3);
            fma2(acc[3][0], xb.y, wd0); fma2(acc[3][1], xb.y, wd1); fma2(acc[3][2], xb.y, wd2); fma2(acc[3][3], xb.y, wd3);
        }
        float4 bq = *(const float4*)&bwp[tx << 2];
        float bj[4] = {bq.x, bq.y, bq.z, bq.w};
        #pragma unroll
        for (int p = 0; p < 4; ++p)
            #pragma unroll
            for (int j = 0; j < 4; ++j) {
                float2 v = upk(acc[p][j]);
                int c = (tx << 2) + j;
                int ta = ty * 8 + 2 * p;
                float va = v.x + bj[j], vb = v.y + bj[j];
                float wa = va / (1.f + __expf(-va));
                float wb = vb / (1.f + __expf(-vb));
                smm[ta * 132 + c] *= wa;
                smm[(ta + 1) * 132 + c] *= wb;
            }
    }
    __syncthreads();
    {
        int rowg = tid >> 4;
        int o4 = (tid & 15) << 2;
        float a2[4][4] = {};
        for (int c = 0; c < DM; c += 4) {
            float4 q0 = *(const float4*)&sopT[(c + 0) * 68 + o4];
            float4 q1 = *(const float4*)&sopT[(c + 1) * 68 + o4];
            float4 q2 = *(const float4*)&sopT[(c + 2) * 68 + o4];
            float4 q3 = *(const float4*)&sopT[(c + 3) * 68 + o4];
            #pragma unroll
            for (int rr = 0; rr < 4; ++rr) {
                float4 pv = *(const float4*)&smm[(rowg * 4 + rr) * 132 + c];
                a2[rr][0] = fmaf(pv.x, q0.x, fmaf(pv.y, q1.x, fmaf(pv.z, q2.x, fmaf(pv.w, q3.x, a2[rr][0]))));
                a2[rr][1] = fmaf(pv.x, q0.y, fmaf(pv.y, q1.y, fmaf(pv.z, q2.y, fmaf(pv.w, q3.y, a2[rr][1]))));
                a2[rr][2] = fmaf(pv.x, q0.z, fmaf(pv.y, q1.z, fmaf(pv.z, q2.z, fmaf(pv.w, q3.z, a2[rr][2]))));
                a2[rr][3] = fmaf(pv.x, q0.w, fmaf(pv.y, q1.w, fmaf(pv.z, q2.w, fmaf(pv.w, q3.w, a2[rr][3]))));
            }
        }
        float4 bq = *(const float4*)&bop[o4];
        #pragma unroll
        for (int rr = 0; rr < 4; ++rr) {
            long tg = t0 + rowg * 4 + rr;
            float4 xq = *(const float4*)&x[tg * DMO + o4];
            float4 ov = make_float4(a2[rr][0] + bq.x + xq.x, a2[rr][1] + bq.y + xq.y,
                                    a2[rr][2] + bq.z + xq.z, a2[rr][3] + bq.w + xq.w);
            *(float4*)&out[tg * DMO + o4] = ov;
        }
    }
}

// ---------------- launch -----------------------------------------------------------
extern "C" void kernel_launch(void* const* d_in, const int* in_sizes, int n_in,
                              void* d_out, int out_size) {
    const float* x    = (const float*)d_in[0];
    const float* wn1  = (const float*)d_in[1];
    const float* wn2  = (const float*)d_in[2];
    const float* Wip  = (const float*)d_in[3];
    const float* bip  = (const float*)d_in[4];
    const float* Wfp  = (const float*)d_in[5];
    const float* bfp  = (const float*)d_in[6];
    const float* Wwp  = (const float*)d_in[7];
    const float* bwp  = (const float*)d_in[8];
    const float* Wop  = (const float*)d_in[9];
    const float* bop  = (const float*)d_in[10];
    const float* Win  = (const float*)d_in[11];
    const float* cw   = (const float*)d_in[12];
    const float* cb   = (const float*)d_in[13];
    const float* Xp   = (const float*)d_in[14];
    const float* Wdt  = (const float*)d_in[15];
    const float* bdt  = (const float*)d_in[16];
    const float* Alog = (const float*)d_in[17];
    const float* Dpar = (const float*)d_in[18];
    const float* Wmo  = (const float*)d_in[19];
    float* out = (float*)d_out;

    const int SM_K1 = (64 * 68 + 64 * 132 + 64) * 4;
    const int SM_K2 = (64 * 68 + 64 * 132 + 128 * 68 + 128) * 4;
    const int SM_K4 = (16640 + 40 * 260 + 64 * 40) * 4;
    const int SM_K6 = (256 * 68 + 256 * 132) * 4;
    const int SM_K7 = (64 * 68 + 64 * 132 + 64 * 132 + 128 * 68) * 4;

    cudaFuncSetAttribute(k_rms_u,   cudaFuncAttributeMaxDynamicSharedMemorySize, SM_K1);
    cudaFuncSetAttribute(k_inproj,  cudaFuncAttributeMaxDynamicSharedMemorySize, SM_K2);
    cudaFuncSetAttribute(k_xproj,   cudaFuncAttributeMaxDynamicSharedMemorySize, SM_K4);
    cudaFuncSetAttribute(k_outproj, cudaFuncAttributeMaxDynamicSharedMemorySize, SM_K6);
    cudaFuncSetAttribute(k_final,   cudaFuncAttributeMaxDynamicSharedMemorySize, SM_K7);

    k_combine<<<32, 256>>>(Wfp, Wip, bip, bfp);
    k_combine2<<<128, 256>>>(Win);
    k_rms_u<<<TOK / 64, 256, SM_K1>>>(x, wn1);
    k_inproj<<<dim3(TOK / 64, 4), 256, SM_K2>>>(cw, cb);
    k_xproj<<<TOK / 64, 256, SM_K4>>>(Xp, Wdt, bdt);
    k_scan1<<<NUNIT / 16, 256>>>(Alog);
    k_scan2<<<64, 256>>>();
    k_scan3<<<NUNIT / 16, 256>>>(Alog, Dpar);
    k_outproj<<<TOK / 64, 256, SM_K6>>>(Wmo, wn2);
    k_final<<<TOK / 64, 256, SM_K7>>>(Wwp, bwp, Wop, bop, x, out);
}

// round 7
// speedup vs baseline: 1.7509x; 1.1777x over previous
#include <cuda_runtime.h>

#define TOK 16384
#define LSEQ 4096
#define NB 4
#define DMO 64      // input/output dim D
#define DM 128      // d_model of mamba (2D)
#define DI 256      // d_inner
#define DS 16       // d_state
#define DTR 8       // dt_rank
#define NCH 1024    // NB * DI channels
#define CHK 64      // chunk length
#define NG (LSEQ / CHK)   // 64 chunks
#define NUNIT (NCH * NG)  // 65536 units

typedef unsigned long long ull;

__device__ __forceinline__ ull pk2(float a, float b) {
    ull r; asm("mov.b64 %0, {%1, %2};" : "=l"(r) : "f"(a), "f"(b)); return r;
}
__device__ __forceinline__ void fma2(ull& d, ull a, ull b) {
    asm("fma.rn.f32x2 %0, %1, %2, %3;" : "=l"(d) : "l"(a), "l"(b), "l"(d));
}
__device__ __forceinline__ float2 upk(ull v) {
    float2 r; asm("mov.b64 {%0, %1}, %2;" : "=f"(r.x), "=f"(r.y) : "l"(v)); return r;
}

// ---------------- scratch ----------------
// xc / zs / delta / y are CHANNEL-MAJOR: [(b*DI + d) * LSEQ + l]
__device__ float g_Wu[DM * DMO];      // W_fp @ W_ip
__device__ float g_bu[DM];            // W_fp @ b_ip + b_fp
__device__ float g_Wc[2 * DI * DMO];  // in_proj @ W_u   (512 x 64)
__device__ float g_bc[2 * DI];        // in_proj @ b_u
__device__ float g_xn[TOK * DMO];
__device__ float g_u[TOK * DM];
__device__ float g_xc[NCH * LSEQ];
__device__ float g_zs[NCH * LSEQ];
__device__ float g_delta[NCH * LSEQ];
__device__ float g_Bm[TOK * DS];
__device__ float g_Cm[TOK * DS];
__device__ float g_y[NCH * LSEQ];
__device__ float g_m[TOK * DM];
__device__ float g_P[NUNIT * DS];
__device__ float g_q[NUNIT * DS];
__device__ float g_hin[NUNIT * DS];

// ---------------- K0: compose W_u = W_fp @ W_ip, b_u = W_fp@b_ip + b_fp ----------
__global__ void k_combine(const float* __restrict__ Wfp, const float* __restrict__ Wip,
                          const float* __restrict__ bip, const float* __restrict__ bfp) {
    int idx = blockIdx.x * 256 + threadIdx.x;
    int o = idx / DMO, i = idx % DMO;
    float s = 0.f;
    for (int k = 0; k < DM; ++k) s = fmaf(Wfp[o * DM + k], Wip[k * DMO + i], s);
    g_Wu[idx] = s;
    if (blockIdx.x == 0 && threadIdx.x < DM) {
        int t = threadIdx.x;
        float sb = bfp[t];
        for (int k = 0; k < DM; ++k) sb = fmaf(Wfp[t * DM + k], bip[k], sb);
        g_bu[t] = sb;
    }
}

// ---------------- K0b: compose W_c = in_proj @ W_u, b_c = in_proj @ b_u ----------
__global__ void k_combine2(const float* __restrict__ Win) {
    int idx = blockIdx.x * 256 + threadIdx.x;   // 128 blocks -> 32768 = 512*64
    int e = idx >> 6, i = idx & 63;
    float s = 0.f;
    for (int k = 0; k < DM; ++k) s = fmaf(Win[(long)e * DM + k], g_Wu[k * DMO + i], s);
    g_Wc[idx] = s;
    if (i == 0) {
        float sb = 0.f;
        for (int k = 0; k < DM; ++k) sb = fmaf(Win[(long)e * DM + k], g_bu[k], sb);
        g_bc[e] = sb;
    }
}

// ---------------- K1: rmsnorm1 + u = W_u @ xn + b_u ------------------------------
__global__ void k_rms_u(const float* __restrict__ x, const float* __restrict__ wn1) {
    extern __shared__ float sm[];
    float* sx  = sm;                 // 64*68 [i][t]
    float* swT = sm + 64 * 68;       // 64*132 [i][o]
    float* ssc = swT + 64 * 132;     // 64
    int tid = threadIdx.x;
    long t0 = (long)blockIdx.x * 64;

    for (int idx = tid; idx < 64 * 64; idx += 256) {
        int i = idx & 63, t = idx >> 6;
        sx[i * 68 + t] = x[(t0 + t) * DMO + i];
    }
    for (int idx = tid; idx < DM * DMO; idx += 256) {
        int i = idx & 63, o = idx >> 6;
        swT[i * 132 + o] = g_Wu[o * DMO + i];
    }
    __syncthreads();
    if (tid < 64) {
        float ss = 0.f;
        for (int i = 0; i < DMO; ++i) { float v = sx[i * 68 + tid]; ss = fmaf(v, v, ss); }
        ssc[tid] = rsqrtf(ss * (1.f / DMO) + 1e-5f);
    }
    __syncthreads();
    for (int idx = tid; idx < 64 * 64; idx += 256) {
        int i = idx & 63, t = idx >> 6;
        float v = sx[i * 68 + t] * ssc[t] * wn1[i];
        sx[i * 68 + t] = v;
        g_xn[(t0 + t) * DMO + i] = v;
    }
    __syncthreads();
    int tx = tid & 31, ty = tid >> 5;
    ull acc[4][4] = {};
    for (int i = 0; i < DMO; ++i) {
        float4 w4 = *(const float4*)&swT[i * 132 + (tx << 2)];
        ull wd0 = pk2(w4.x, w4.x), wd1 = pk2(w4.y, w4.y);
        ull wd2 = pk2(w4.z, w4.z), wd3 = pk2(w4.w, w4.w);
        ulonglong2 xa = *(const ulonglong2*)&sx[i * 68 + ty * 8];
        ulonglong2 xb = *(const ulonglong2*)&sx[i * 68 + ty * 8 + 4];
        fma2(acc[0][0], xa.x, wd0); fma2(acc[0][1], xa.x, wd1); fma2(acc[0][2], xa.x, wd2); fma2(acc[0][3], xa.x, wd3);
        fma2(acc[1][0], xa.y, wd0); fma2(acc[1][1], xa.y, wd1); fma2(acc[1][2], xa.y, wd2); fma2(acc[1][3], xa.y, wd3);
        fma2(acc[2][0], xb.x, wd0); fma2(acc[2][1], xb.x, wd1); fma2(acc[2][2], xb.x, wd2); fma2(acc[2][3], xb.x, wd3);
        fma2(acc[3][0], xb.y, wd0); fma2(acc[3][1], xb.y, wd1); fma2(acc[3][2], xb.y, wd2); fma2(acc[3][3], xb.y, wd3);
    }
    float4 bq = *(const float4*)&g_bu[tx << 2];
    #pragma unroll
    for (int p = 0; p < 4; ++p) {
        float2 v0 = upk(acc[p][0]), v1 = upk(acc[p][1]), v2 = upk(acc[p][2]), v3 = upk(acc[p][3]);
        long ta = t0 + ty * 8 + 2 * p, tb = ta + 1;
        float4 lo = make_float4(v0.x + bq.x, v1.x + bq.y, v2.x + bq.z, v3.x + bq.w);
        float4 hi = make_float4(v0.y + bq.x, v1.y + bq.y, v2.y + bq.z, v3.y + bq.w);
        *(float4*)&g_u[ta * DM + (tx << 2)] = lo;
        *(float4*)&g_u[tb * DM + (tx << 2)] = hi;
    }
}

// ---------------- K2: xz = W_c @ xn + b_c ; fused conv+silu (x) / silu (z) --------
// Stage buffer reuses the dead sxn/swT region after the GEMM (halo kept in regs).
__global__ void k_inproj(const float* __restrict__ cw, const float* __restrict__ cb) {
    extern __shared__ float sm[];
    float* sxn   = sm;                 // [i][t] 64*68 ; cols 0-63 main, 64-66 halo
    float* swT   = sm + 64 * 68;       // [i][e] 64*132
    float* sbc   = sm + 12800;         // 128 biases (persists)
    float* stage = sm;                 // [e][t'] 128*68 AFTER GEMM (reuse)
    int tid = threadIdx.x;
    long t0 = (long)blockIdx.x * 64;
    int e0 = blockIdx.y * 128;
    int b = (int)(t0 >> 12);
    int l0 = (int)(t0 & (LSEQ - 1));
    bool isx = (e0 < DI);

    for (int idx = tid; idx < 64 * 64; idx += 256) {
        int i = idx & 63, t = idx >> 6;
        sxn[i * 68 + t] = g_xn[(t0 + t) * DMO + i];
    }
    for (int idx = tid; idx < 128 * 64; idx += 256) {
        int i = idx & 63, e = idx >> 6;
        swT[i * 132 + e] = g_Wc[(long)(e0 + e) * DMO + i];
    }
    if (tid < 128) sbc[tid] = g_bc[e0 + tid];
    if (isx && tid < 192) {   // halo xn: tokens t0-3..t0-1
        int i = tid & 63, j = tid >> 6;
        sxn[i * 68 + 64 + j] = (l0 > 0) ? g_xn[(t0 - 3 + j) * DMO + i] : 0.f;
    }
    __syncthreads();
    int tx = tid & 31, ty = tid >> 5;
    ull acc[4][4] = {};
    for (int i = 0; i < 64; ++i) {
        float4 w4 = *(const float4*)&swT[i * 132 + (tx << 2)];
        ull wd0 = pk2(w4.x, w4.x), wd1 = pk2(w4.y, w4.y);
        ull wd2 = pk2(w4.z, w4.z), wd3 = pk2(w4.w, w4.w);
        ulonglong2 xa = *(const ulonglong2*)&sxn[i * 68 + ty * 8];
        ulonglong2 xb = *(const ulonglong2*)&sxn[i * 68 + ty * 8 + 4];
        fma2(acc[0][0], xa.x, wd0); fma2(acc[0][1], xa.x, wd1); fma2(acc[0][2], xa.x, wd2); fma2(acc[0][3], xa.x, wd3);
        fma2(acc[1][0], xa.y, wd0); fma2(acc[1][1], xa.y, wd1); fma2(acc[1][2], xa.y, wd2); fma2(acc[1][3], xa.y, wd3);
        fma2(acc[2][0], xb.x, wd0); fma2(acc[2][1], xb.x, wd1); fma2(acc[2][2], xb.x, wd2); fma2(acc[2][3], xb.x, wd3);
        fma2(acc[3][0], xb.y, wd0); fma2(acc[3][1], xb.y, wd1); fma2(acc[3][2], xb.y, wd2); fma2(acc[3][3], xb.y, wd3);
    }
    // halo xz values -> registers (x blocks only)
    float h1 = 0.f, h2 = 0.f;
    if (isx && l0 > 0) {
        {
            int j = tid >> 7, e = tid & 127;
            float a = sbc[e];
            for (int i = 0; i < 64; ++i)
                a = fmaf(sxn[i * 68 + 64 + j], swT[i * 132 + e], a);
            h1 = a;
        }
        if (tid < 128) {
            int e = tid;
            float a = sbc[e];
            for (int i = 0; i < 64; ++i)
                a = fmaf(sxn[i * 68 + 66], swT[i * 132 + e], a);
            h2 = a;
        }
    }
    __syncthreads();   // all reads of sxn/swT done -> reuse as stage
    #pragma unroll
    for (int p = 0; p < 4; ++p)
        #pragma unroll
        for (int j = 0; j < 4; ++j) {
            float2 v = upk(acc[p][j]);
            int e = (tx << 2) + j, t = ty * 8 + 2 * p;
            float bce = sbc[e];
            stage[e * 68 + 3 + t] = v.x + bce;
            stage[e * 68 + 4 + t] = v.y + bce;
        }
    if (isx) {
        { int j = tid >> 7, e = tid & 127; stage[e * 68 + j] = h1; }
        if (tid < 128) stage[tid * 68 + 2] = h2;
    }
    __syncthreads();
    if (isx) {
        for (int idx = tid; idx < 128 * 64; idx += 256) {
            int t = idx & 63, e = idx >> 6;
            int d = e0 + e;
            const float* st = &stage[e * 68];
            float4 w = *(const float4*)&cw[d * 4];
            float a = cb[d];
            a = fmaf(w.x, st[t], a);
            a = fmaf(w.y, st[t + 1], a);
            a = fmaf(w.z, st[t + 2], a);
            a = fmaf(w.w, st[t + 3], a);
            a = a / (1.f + __expf(-a));
            g_xc[(long)(b * DI + d) * LSEQ + l0 + t] = a;
        }
    } else {
        for (int idx = tid; idx < 128 * 64; idx += 256) {
            int t = idx & 63, e = idx >> 6;
            float v = stage[e * 68 + 3 + t];
            v = v / (1.f + __expf(-v));
            g_zs[(long)(b * DI + (e0 - DI) + e) * LSEQ + l0 + t] = v;
        }
    }
}

// ---------------- K4: x_dbl = x_proj @ x ; B,C ; delta (K-chunked, smem reuse) ---
__global__ void k_xproj(const float* __restrict__ Xp, const float* __restrict__ Wdt,
                        const float* __restrict__ bdt) {
    extern __shared__ float sm[];
    float* sdbl = sm;                 // 64*40 (persists)
    float* sxc  = sm + 2560;          // phase1: [t][kk] 64*132
    float* spc  = sm + 2560 + 8448;   // phase1: [e][kk] 40*132
    float* sdel = sm + 2560;          // phase2: [d][t] 256*65 (reuses chunk region)
    int tid = threadIdx.x;
    long t0 = (long)blockIdx.x * 64;
    int b = (int)(t0 >> 12);
    int l0 = (int)(t0 & (LSEQ - 1));

    int tt = tid >> 2, eb = (tid & 3) * 10;
    float acc[10] = {};
    for (int kc = 0; kc < 2; ++kc) {
        __syncthreads();
        for (int idx = tid; idx < 64 * 128; idx += 256) {
            int t = idx & 63, kk = idx >> 6;
            sxc[t * 132 + kk] = g_xc[(long)(b * DI + kc * 128 + kk) * LSEQ + l0 + t];
        }
        for (int idx = tid; idx < 40 * 128; idx += 256) {
            int kk = idx & 127, e = idx >> 7;
            spc[e * 132 + kk] = Xp[e * DI + kc * 128 + kk];
        }
        __syncthreads();
        for (int kk = 0; kk < 128; kk += 4) {
            float4 xv = *(const float4*)&sxc[tt * 132 + kk];
            #pragma unroll
            for (int e = 0; e < 10; ++e) {
                float4 wv = *(const float4*)&spc[(eb + e) * 132 + kk];
                acc[e] = fmaf(xv.x, wv.x, fmaf(xv.y, wv.y, fmaf(xv.z, wv.z, fmaf(xv.w, wv.w, acc[e]))));
            }
        }
    }
    __syncthreads();
    #pragma unroll
    for (int e = 0; e < 10; ++e) sdbl[tt * 40 + eb + e] = acc[e];
    __syncthreads();
    for (int idx = tid; idx < 64 * DS; idx += 256) {
        int t = idx >> 4, s = idx & 15;
        g_Bm[(t0 + t) * DS + s] = sdbl[t * 40 + 8 + s];
        g_Cm[(t0 + t) * DS + s] = sdbl[t * 40 + 24 + s];
    }
    {
        int d = tid;
        float wr[8];
        #pragma unroll
        for (int r = 0; r < 8; ++r) wr[r] = Wdt[d * 8 + r];
        float bb = bdt[d];
        for (int t = 0; t < 64; ++t) {
            float pre = bb;
            #pragma unroll
            for (int r = 0; r < 8; ++r) pre = fmaf(sdbl[t * 40 + r], wr[r], pre);
            float sp = (pre > 20.f) ? pre : log1pf(__expf(pre));
            sdel[d * 65 + t] = sp;
        }
    }
    __syncthreads();
    for (int idx = tid; idx < DI * 64; idx += 256) {
        int d = idx >> 6, t = idx & 63;
        g_delta[(long)(b * DI + d) * LSEQ + l0 + t] = sdel[d * 65 + t];
    }
}

// ---------------- K5a: per-chunk decay product P and local state q ----------------
__global__ void k_scan1(const float* __restrict__ Alog) {
    int u = threadIdx.x >> 4;
    int s = threadIdx.x & 15;
    int unit = blockIdx.x * 16 + u;
    int g = unit & (NG - 1);
    int ch = unit >> 6;
    int b = ch >> 8, d = ch & 255;
    float Aval = -__expf(Alog[d * DS + s]);
    const float* pd = g_delta + (long)ch * LSEQ + g * CHK;
    const float* px = g_xc    + (long)ch * LSEQ + g * CHK;
    const float* pB = g_Bm    + ((long)b * LSEQ + g * CHK) * DS + s;
    float P = 1.f, q = 0.f;
    #pragma unroll 8
    for (int t = 0; t < CHK; ++t) {
        float dv = pd[t];
        float xv = px[t];
        float Bv = pB[t * DS];
        float a = __expf(dv * Aval);
        P *= a;
        q = fmaf(a, q, dv * xv * Bv);
    }
    long idx = (long)unit * DS + s;
    g_P[idx] = P;
    g_q[idx] = q;
}

// ---------------- K5b: propagate h_in across chunks ------------------------------
__global__ void k_scan2() {
    int tid = blockIdx.x * 256 + threadIdx.x;
    int ch = tid >> 4, s = tid & 15;
    float h = 0.f;
    long base = (long)ch * NG * DS + s;
    #pragma unroll 8
    for (int g = 0; g < NG; ++g) {
        long idx = base + (long)g * DS;
        g_hin[idx] = h;
        h = fmaf(g_P[idx], h, g_q[idx]);
    }
}

// ---------------- K5c: local scan from h_in, y = (C.h + x*D) * silu(z) -----------
__global__ void k_scan3(const float* __restrict__ Alog, const float* __restrict__ Dp_) {
    __shared__ float ybuf[16 * CHK];
    int u = threadIdx.x >> 4;
    int s = threadIdx.x & 15;
    int unit = blockIdx.x * 16 + u;
    int g = unit & (NG - 1);
    int ch = unit >> 6;
    int b = ch >> 8, d = ch & 255;
    float Aval = -__expf(Alog[d * DS + s]);
    float Dp = Dp_[d];
    const float* pd = g_delta + (long)ch * LSEQ + g * CHK;
    const float* px = g_xc    + (long)ch * LSEQ + g * CHK;
    const float* pz = g_zs    + (long)ch * LSEQ + g * CHK;
    const float* pB = g_Bm    + ((long)b * LSEQ + g * CHK) * DS + s;
    const float* pC = g_Cm    + ((long)b * LSEQ + g * CHK) * DS + s;
    float h = g_hin[(long)unit * DS + s];
    #pragma unroll 4
    for (int t = 0; t < CHK; ++t) {
        float dv = pd[t];
        float xv = px[t];
        float Bv = pB[t * DS];
        float Cv = pC[t * DS];
        float a = __expf(dv * Aval);
        h = fmaf(a, h, dv * xv * Bv);
        float p = h * Cv;
        p += __shfl_xor_sync(0xffffffffu, p, 8);
        p += __shfl_xor_sync(0xffffffffu, p, 4);
        p += __shfl_xor_sync(0xffffffffu, p, 2);
        p += __shfl_xor_sync(0xffffffffu, p, 1);
        if (s == 0) ybuf[u * CHK + t] = (p + xv * Dp) * pz[t];
    }
    __syncthreads();
    float* py = g_y + (long)ch * LSEQ + (long)(blockIdx.x & 3) * 1024;
    for (int i = threadIdx.x; i < 16 * CHK; i += 256) py[i] = ybuf[i];
}

// ---------------- K6: m = rmsnorm2(mamba_out @ y) + u (K-chunked) ----------------
__global__ void k_outproj(const float* __restrict__ Wmo, const float* __restrict__ wn2) {
    extern __shared__ float sm[];
    float* syT = sm;               // [k][t] 64*68 chunk
    float* swT = sm + 64 * 68;     // [k][o] 64*132 chunk
    int tid = threadIdx.x;
    long t0 = (long)blockIdx.x * 64;
    int b = (int)(t0 >> 12);
    int lpos = (int)(t0 & (LSEQ - 1));
    int tx = tid & 31, ty = tid >> 5;

    ull acc[4][4] = {};
    for (int kc = 0; kc < 4; ++kc) {
        __syncthreads();
        for (int idx = tid; idx < 64 * 64; idx += 256) {
            int t = idx & 63, k = idx >> 6;
            syT[k * 68 + t] = g_y[(long)(b * DI + kc * 64 + k) * LSEQ + lpos + t];
        }
        for (int idx = tid; idx < 64 * DM; idx += 256) {
            int k = idx & 63, o = idx >> 6;
            swT[k * 132 + o] = Wmo[(long)o * DI + kc * 64 + k];
        }
        __syncthreads();
        for (int k = 0; k < 64; ++k) {
            float4 w4 = *(const float4*)&swT[k * 132 + (tx << 2)];
            ull wd0 = pk2(w4.x, w4.x), wd1 = pk2(w4.y, w4.y);
            ull wd2 = pk2(w4.z, w4.z), wd3 = pk2(w4.w, w4.w);
            ulonglong2 xa = *(const ulonglong2*)&syT[k * 68 + ty * 8];
            ulonglong2 xb = *(const ulonglong2*)&syT[k * 68 + ty * 8 + 4];
            fma2(acc[0][0], xa.x, wd0); fma2(acc[0][1], xa.x, wd1); fma2(acc[0][2], xa.x, wd2); fma2(acc[0][3], xa.x, wd3);
            fma2(acc[1][0], xa.y, wd0); fma2(acc[1][1], xa.y, wd1); fma2(acc[1][2], xa.y, wd2); fma2(acc[1][3], xa.y, wd3);
            fma2(acc[2][0], xb.x, wd0); fma2(acc[2][1], xb.x, wd1); fma2(acc[2][2], xb.x, wd2); fma2(acc[2][3], xb.x, wd3);
            fma2(acc[3][0], xb.y, wd0); fma2(acc[3][1], xb.y, wd1); fma2(acc[3][2], xb.y, wd2); fma2(acc[3][3], xb.y, wd3);
        }
    }
    float af[8][4];
    #pragma unroll
    for (int p = 0; p < 4; ++p)
        #pragma unroll
        for (int j = 0; j < 4; ++j) {
            float2 v = upk(acc[p][j]);
            af[2 * p][j] = v.x;
            af[2 * p + 1][j] = v.y;
        }
    float4 w2q = *(const float4*)&wn2[tx << 2];
    #pragma unroll
    for (int r = 0; r < 8; ++r) {
        float ss = 0.f;
        #pragma unroll
        for (int j = 0; j < 4; ++j) ss = fmaf(af[r][j], af[r][j], ss);
        #pragma unroll
        for (int off = 16; off >= 1; off >>= 1) ss += __shfl_xor_sync(0xffffffffu, ss, off);
        float sc = rsqrtf(ss * (1.f / DM) + 1e-5f);
        long t = t0 + ty * 8 + r;
        float4 uq = *(const float4*)&g_u[t * DM + (tx << 2)];
        float4 ov = make_float4(af[r][0] * sc * w2q.x + uq.x,
                                af[r][1] * sc * w2q.y + uq.y,
                                af[r][2] * sc * w2q.z + uq.z,
                                af[r][3] * sc * w2q.w + uq.w);
        *(float4*)&g_m[t * DM + (tx << 2)] = ov;
    }
}

// ---------------- K7: w = swish(W_wp@xn+b) ; out = W_op@(w*m)+b + x ---------------
// sopT loads into the dead sxn/swpT region after GEMM-1.
__global__ void k_final(const float* __restrict__ Wwp, const float* __restrict__ bwp,
                        const float* __restrict__ Wop, const float* __restrict__ bop,
                        const float* __restrict__ x, float* __restrict__ out) {
    extern __shared__ float sm[];
    float* smm  = sm;                      // [t][c] 64*132 (persists)
    float* sxn  = sm + 64 * 132;           // [i][t] 64*68 (phase 1)
    float* swpT = sm + 64 * 132 + 64 * 68; // [i][c] 64*132 (phase 1)
    float* sopT = sm + 64 * 132;           // [c][o] 128*68 (phase 2, reuse)
    int tid = threadIdx.x;
    long t0 = (long)blockIdx.x * 64;

    for (int idx = tid; idx < 64 * DM; idx += 256) {
        int c = idx & 127, t = idx >> 7;
        smm[t * 132 + c] = g_m[(t0 + t) * DM + c];
    }
    for (int idx = tid; idx < 64 * 64; idx += 256) {
        int i = idx & 63, t = idx >> 6;
        sxn[i * 68 + t] = g_xn[(t0 + t) * DMO + i];
    }
    for (int idx = tid; idx < DM * DMO; idx += 256) {
        int i = idx & 63, c = idx >> 6;
        swpT[i * 132 + c] = Wwp[c * DMO + i];
    }
    __syncthreads();
    int tx = tid & 31, ty = tid >> 5;
    {
        ull acc[4][4] = {};
        for (int i = 0; i < DMO; ++i) {
            float4 w4 = *(const float4*)&swpT[i * 132 + (tx << 2)];
            ull wd0 = pk2(w4.x, w4.x), wd1 = pk2(w4.y, w4.y);
            ull wd2 = pk2(w4.z, w4.z), wd3 = pk2(w4.w, w4.w);
            ulonglong2 xa = *(const ulonglong2*)&sxn[i * 68 + ty * 8];
            ulonglong2 xb = *(const ulonglong2*)&sxn[i * 68 + ty * 8 + 4];
            fma2(acc[0][0], xa.x, wd0); fma2(acc[0][1], xa.x, wd1); fma2(acc[0][2], xa.x, wd2); fma2(acc[0][3], xa.x, wd3);
            fma2(acc[1][0], xa.y, wd0); fma2(acc[1][1], xa.y, wd1); fma2(acc[1][2], xa.y, wd2); fma2(acc[1][3], xa.y, wd3);
            fma2(acc[2][0], xb.x, wd0); fma2(acc[2][1], xb.x, wd1); fma2(acc[2][2], xb.x, wd2); fma2(acc[2][3], xb.x, wd3);
            fma2(acc[3][0], xb.y, wd0); fma2(acc[3][1], xb.y, wd1); fma2(acc[3][2], xb.y, wd2); fma2(acc[3][3], xb.y, wd3);
        }
        float4 bq = *(const float4*)&bwp[tx << 2];
        float bj[4] = {bq.x, bq.y, bq.z, bq.w};
        #pragma unroll
        for (int p = 0; p < 4; ++p)
            #pragma unroll
            for (int j = 0; j < 4; ++j) {
                float2 v = upk(acc[p][j]);
                int c = (tx << 2) + j;
                int ta = ty * 8 + 2 * p;
                float va = v.x + bj[j], vb = v.y + bj[j];
                float wa = va / (1.f + __expf(-va));
                float wb = vb / (1.f + __expf(-vb));
                smm[ta * 132 + c] *= wa;
                smm[(ta + 1) * 132 + c] *= wb;
            }
    }
    __syncthreads();   // sxn/swpT dead -> load sopT
    for (int idx = tid; idx < DMO * DM; idx += 256) {
        int c = idx & 127, o = idx >> 7;
        sopT[c * 68 + o] = Wop[o * DM + c];
    }
    __syncthreads();
    {
        int rowg = tid >> 4;
        int o4 = (tid & 15) << 2;
        float a2[4][4] = {};
        for (int c = 0; c < DM; c += 4) {
            float4 q0 = *(const float4*)&sopT[(c + 0) * 68 + o4];
            float4 q1 = *(const float4*)&sopT[(c + 1) * 68 + o4];
            float4 q2 = *(const float4*)&sopT[(c + 2) * 68 + o4];
            float4 q3 = *(const float4*)&sopT[(c + 3) * 68 + o4];
            #pragma unroll
            for (int rr = 0; rr < 4; ++rr) {
                float4 pv = *(const float4*)&smm[(rowg * 4 + rr) * 132 + c];
                a2[rr][0] = fmaf(pv.x, q0.x, fmaf(pv.y, q1.x, fmaf(pv.z, q2.x, fmaf(pv.w, q3.x, a2[rr][0]))));
                a2[rr][1] = fmaf(pv.x, q0.y, fmaf(pv.y, q1.y, fmaf(pv.z, q2.y, fmaf(pv.w, q3.y, a2[rr][1]))));
                a2[rr][2] = fmaf(pv.x, q0.z, fmaf(pv.y, q1.z, fmaf(pv.z, q2.z, fmaf(pv.w, q3.z, a2[rr][2]))));
                a2[rr][3] = fmaf(pv.x, q0.w, fmaf(pv.y, q1.w, fmaf(pv.z, q2.w, fmaf(pv.w, q3.w, a2[rr][3]))));
            }
        }
        float4 bq = *(const float4*)&bop[o4];
        #pragma unroll
        for (int rr = 0; rr < 4; ++rr) {
            long tg = t0 + rowg * 4 + rr;
            float4 xq = *(const float4*)&x[tg * DMO + o4];
            float4 ov = make_float4(a2[rr][0] + bq.x + xq.x, a2[rr][1] + bq.y + xq.y,
                                    a2[rr][2] + bq.z + xq.z, a2[rr][3] + bq.w + xq.w);
            *(float4*)&out[tg * DMO + o4] = ov;
        }
    }
}

// ---------------- launch -----------------------------------------------------------
extern "C" void kernel_launch(void* const* d_in, const int* in_sizes, int n_in,
                              void* d_out, int out_size) {
    const float* x    = (const float*)d_in[0];
    const float* wn1  = (const float*)d_in[1];
    const float* wn2  = (const float*)d_in[2];
    const float* Wip  = (const float*)d_in[3];
    const float* bip  = (const float*)d_in[4];
    const float* Wfp  = (const float*)d_in[5];
    const float* bfp  = (const float*)d_in[6];
    const float* Wwp  = (const float*)d_in[7];
    const float* bwp  = (const float*)d_in[8];
    const float* Wop  = (const float*)d_in[9];
    const float* bop  = (const float*)d_in[10];
    const float* Win  = (const float*)d_in[11];
    const float* cw   = (const float*)d_in[12];
    const float* cb   = (const float*)d_in[13];
    const float* Xp   = (const float*)d_in[14];
    const float* Wdt  = (const float*)d_in[15];
    const float* bdt  = (const float*)d_in[16];
    const float* Alog = (const float*)d_in[17];
    const float* Dpar = (const float*)d_in[18];
    const float* Wmo  = (const float*)d_in[19];
    float* out = (float*)d_out;

    const int SM_K1 = (64 * 68 + 64 * 132 + 64) * 4;     // 51.5 KB -> 4 CTA/SM
    const int SM_K2 = (12800 + 128) * 4;                  // 51.7 KB -> 4 CTA/SM
    const int SM_K4 = (2560 + 256 * 65) * 4;              // 76.8 KB -> 2 CTA/SM
    const int SM_K6 = (64 * 68 + 64 * 132) * 4;           // 51.2 KB -> 4 CTA/SM
    const int SM_K7 = (64 * 132 + 64 * 68 + 64 * 132) * 4;// 85.0 KB -> 2 CTA/SM

    cudaFuncSetAttribute(k_rms_u,   cudaFuncAttributeMaxDynamicSharedMemorySize, SM_K1);
    cudaFuncSetAttribute(k_inproj,  cudaFuncAttributeMaxDynamicSharedMemorySize, SM_K2);
    cudaFuncSetAttribute(k_xproj,   cudaFuncAttributeMaxDynamicSharedMemorySize, SM_K4);
    cudaFuncSetAttribute(k_outproj, cudaFuncAttributeMaxDynamicSharedMemorySize, SM_K6);
    cudaFuncSetAttribute(k_final,   cudaFuncAttributeMaxDynamicSharedMemorySize, SM_K7);

    k_combine<<<32, 256>>>(Wfp, Wip, bip, bfp);
    k_combine2<<<128, 256>>>(Win);
    k_rms_u<<<TOK / 64, 256, SM_K1>>>(x, wn1);
    k_inproj<<<dim3(TOK / 64, 4), 256, SM_K2>>>(cw, cb);
    k_xproj<<<TOK / 64, 256, SM_K4>>>(Xp, Wdt, bdt);
    k_scan1<<<NUNIT / 16, 256>>>(Alog);
    k_scan2<<<64, 256>>>();
    k_scan3<<<NUNIT / 16, 256>>>(Alog, Dpar);
    k_outproj<<<TOK / 64, 256, SM_K6>>>(Wmo, wn2);
    k_final<<<TOK / 64, 256, SM_K7>>>(Wwp, bwp, Wop, bop, x, out);
}

// round 8
// speedup vs baseline: 1.8852x; 1.0767x over previous
#include <cuda_runtime.h>

#define TOK 16384
#define LSEQ 4096
#define NB 4
#define DMO 64      // input/output dim D
#define DM 128      // d_model of mamba (2D)
#define DI 256      // d_inner
#define DS 16       // d_state
#define DTR 8       // dt_rank
#define NCH 1024    // NB * DI channels
#define CHK 64      // chunk length
#define NG (LSEQ / CHK)   // 64 chunks
#define NUNIT (NCH * NG)  // 65536 units

typedef unsigned long long ull;

__device__ __forceinline__ ull pk2(float a, float b) {
    ull r; asm("mov.b64 %0, {%1, %2};" : "=l"(r) : "f"(a), "f"(b)); return r;
}
__device__ __forceinline__ void fma2(ull& d, ull a, ull b) {
    asm("fma.rn.f32x2 %0, %1, %2, %3;" : "=l"(d) : "l"(a), "l"(b), "l"(d));
}
__device__ __forceinline__ float2 upk(ull v) {
    float2 r; asm("mov.b64 {%0, %1}, %2;" : "=f"(r.x), "=f"(r.y) : "l"(v)); return r;
}

// ---------------- scratch ----------------
// xc / zs / delta / y are CHANNEL-MAJOR: [(b*DI + d) * LSEQ + l]
__device__ float g_Wu[DM * DMO];      // W_fp @ W_ip
__device__ float g_bu[DM];            // W_fp @ b_ip + b_fp
__device__ float g_Wc[2 * DI * DMO];  // in_proj @ W_u   (512 x 64)
__device__ float g_bc[2 * DI];        // in_proj @ b_u
__device__ float g_xn[TOK * DMO];
__device__ float g_u[TOK * DM];
__device__ float g_xc[NCH * LSEQ];
__device__ float g_zs[NCH * LSEQ];
__device__ float g_delta[NCH * LSEQ];
__device__ float g_Bm[TOK * DS];
__device__ float g_Cm[TOK * DS];
__device__ float g_y[NCH * LSEQ];
__device__ float g_m[TOK * DM];
__device__ float g_P[NUNIT * DS];
__device__ float g_q[NUNIT * DS];
__device__ float g_hin[NUNIT * DS];

// ---------------- K0: compose W_u = W_fp @ W_ip, b_u = W_fp@b_ip + b_fp ----------
__global__ void k_combine(const float* __restrict__ Wfp, const float* __restrict__ Wip,
                          const float* __restrict__ bip, const float* __restrict__ bfp) {
    int idx = blockIdx.x * 256 + threadIdx.x;
    int o = idx / DMO, i = idx % DMO;
    float s = 0.f;
    for (int k = 0; k < DM; ++k) s = fmaf(Wfp[o * DM + k], Wip[k * DMO + i], s);
    g_Wu[idx] = s;
    if (blockIdx.x == 0 && threadIdx.x < DM) {
        int t = threadIdx.x;
        float sb = bfp[t];
        for (int k = 0; k < DM; ++k) sb = fmaf(Wfp[t * DM + k], bip[k], sb);
        g_bu[t] = sb;
    }
}

// ---------------- K0b: compose W_c = in_proj @ W_u, b_c = in_proj @ b_u ----------
__global__ void k_combine2(const float* __restrict__ Win) {
    int idx = blockIdx.x * 256 + threadIdx.x;   // 128 blocks -> 32768 = 512*64
    int e = idx >> 6, i = idx & 63;
    float s = 0.f;
    for (int k = 0; k < DM; ++k) s = fmaf(Win[(long)e * DM + k], g_Wu[k * DMO + i], s);
    g_Wc[idx] = s;
    if (i == 0) {
        float sb = 0.f;
        for (int k = 0; k < DM; ++k) sb = fmaf(Win[(long)e * DM + k], g_bu[k], sb);
        g_bc[e] = sb;
    }
}

// ---------------- K1: rmsnorm1 + u = W_u @ xn + b_u ------------------------------
__global__ void __launch_bounds__(256, 4)
k_rms_u(const float* __restrict__ x, const float* __restrict__ wn1) {
    extern __shared__ float sm[];
    float* sx  = sm;                 // 64*68 [i][t]
    float* swT = sm + 64 * 68;       // 64*132 [i][o]
    float* ssc = swT + 64 * 132;     // 64
    int tid = threadIdx.x;
    long t0 = (long)blockIdx.x * 64;

    for (int idx = tid; idx < 64 * 64; idx += 256) {
        int i = idx & 63, t = idx >> 6;
        sx[i * 68 + t] = x[(t0 + t) * DMO + i];
    }
    for (int idx = tid; idx < DM * DMO; idx += 256) {
        int i = idx & 63, o = idx >> 6;
        swT[i * 132 + o] = g_Wu[o * DMO + i];
    }
    __syncthreads();
    if (tid < 64) {
        float ss = 0.f;
        for (int i = 0; i < DMO; ++i) { float v = sx[i * 68 + tid]; ss = fmaf(v, v, ss); }
        ssc[tid] = rsqrtf(ss * (1.f / DMO) + 1e-5f);
    }
    __syncthreads();
    for (int idx = tid; idx < 64 * 64; idx += 256) {
        int i = idx & 63, t = idx >> 6;
        float v = sx[i * 68 + t] * ssc[t] * wn1[i];
        sx[i * 68 + t] = v;
        g_xn[(t0 + t) * DMO + i] = v;
    }
    __syncthreads();
    int tx = tid & 31, ty = tid >> 5;
    ull acc[4][4] = {};
    for (int i = 0; i < DMO; ++i) {
        float4 w4 = *(const float4*)&swT[i * 132 + (tx << 2)];
        ull wd0 = pk2(w4.x, w4.x), wd1 = pk2(w4.y, w4.y);
        ull wd2 = pk2(w4.z, w4.z), wd3 = pk2(w4.w, w4.w);
        ulonglong2 xa = *(const ulonglong2*)&sx[i * 68 + ty * 8];
        ulonglong2 xb = *(const ulonglong2*)&sx[i * 68 + ty * 8 + 4];
        fma2(acc[0][0], xa.x, wd0); fma2(acc[0][1], xa.x, wd1); fma2(acc[0][2], xa.x, wd2); fma2(acc[0][3], xa.x, wd3);
        fma2(acc[1][0], xa.y, wd0); fma2(acc[1][1], xa.y, wd1); fma2(acc[1][2], xa.y, wd2); fma2(acc[1][3], xa.y, wd3);
        fma2(acc[2][0], xb.x, wd0); fma2(acc[2][1], xb.x, wd1); fma2(acc[2][2], xb.x, wd2); fma2(acc[2][3], xb.x, wd3);
        fma2(acc[3][0], xb.y, wd0); fma2(acc[3][1], xb.y, wd1); fma2(acc[3][2], xb.y, wd2); fma2(acc[3][3], xb.y, wd3);
    }
    float4 bq = *(const float4*)&g_bu[tx << 2];
    #pragma unroll
    for (int p = 0; p < 4; ++p) {
        float2 v0 = upk(acc[p][0]), v1 = upk(acc[p][1]), v2 = upk(acc[p][2]), v3 = upk(acc[p][3]);
        long ta = t0 + ty * 8 + 2 * p, tb = ta + 1;
        float4 lo = make_float4(v0.x + bq.x, v1.x + bq.y, v2.x + bq.z, v3.x + bq.w);
        float4 hi = make_float4(v0.y + bq.x, v1.y + bq.y, v2.y + bq.z, v3.y + bq.w);
        *(float4*)&g_u[ta * DM + (tx << 2)] = lo;
        *(float4*)&g_u[tb * DM + (tx << 2)] = hi;
    }
}

// ---------------- K2: xz = W_c @ xn + b_c ; fused conv+silu (x) / silu (z) --------
__global__ void __launch_bounds__(256, 4)
k_inproj(const float* __restrict__ cw, const float* __restrict__ cb) {
    extern __shared__ float sm[];
    float* sxn   = sm;                 // [i][t] 64*68 ; cols 0-63 main, 64-66 halo
    float* swT   = sm + 64 * 68;       // [i][e] 64*132
    float* sbc   = sm + 12800;         // 128 biases (persists)
    float* stage = sm;                 // [e][t'] 128*68 AFTER GEMM (reuse)
    int tid = threadIdx.x;
    long t0 = (long)blockIdx.x * 64;
    int e0 = blockIdx.y * 128;
    int b = (int)(t0 >> 12);
    int l0 = (int)(t0 & (LSEQ - 1));
    bool isx = (e0 < DI);

    for (int idx = tid; idx < 64 * 64; idx += 256) {
        int i = idx & 63, t = idx >> 6;
        sxn[i * 68 + t] = g_xn[(t0 + t) * DMO + i];
    }
    for (int idx = tid; idx < 128 * 64; idx += 256) {
        int i = idx & 63, e = idx >> 6;
        swT[i * 132 + e] = g_Wc[(long)(e0 + e) * DMO + i];
    }
    if (tid < 128) sbc[tid] = g_bc[e0 + tid];
    if (isx && tid < 192) {   // halo xn: tokens t0-3..t0-1
        int i = tid & 63, j = tid >> 6;
        sxn[i * 68 + 64 + j] = (l0 > 0) ? g_xn[(t0 - 3 + j) * DMO + i] : 0.f;
    }
    __syncthreads();
    int tx = tid & 31, ty = tid >> 5;
    ull acc[4][4] = {};
    for (int i = 0; i < 64; ++i) {
        float4 w4 = *(const float4*)&swT[i * 132 + (tx << 2)];
        ull wd0 = pk2(w4.x, w4.x), wd1 = pk2(w4.y, w4.y);
        ull wd2 = pk2(w4.z, w4.z), wd3 = pk2(w4.w, w4.w);
        ulonglong2 xa = *(const ulonglong2*)&sxn[i * 68 + ty * 8];
        ulonglong2 xb = *(const ulonglong2*)&sxn[i * 68 + ty * 8 + 4];
        fma2(acc[0][0], xa.x, wd0); fma2(acc[0][1], xa.x, wd1); fma2(acc[0][2], xa.x, wd2); fma2(acc[0][3], xa.x, wd3);
        fma2(acc[1][0], xa.y, wd0); fma2(acc[1][1], xa.y, wd1); fma2(acc[1][2], xa.y, wd2); fma2(acc[1][3], xa.y, wd3);
        fma2(acc[2][0], xb.x, wd0); fma2(acc[2][1], xb.x, wd1); fma2(acc[2][2], xb.x, wd2); fma2(acc[2][3], xb.x, wd3);
        fma2(acc[3][0], xb.y, wd0); fma2(acc[3][1], xb.y, wd1); fma2(acc[3][2], xb.y, wd2); fma2(acc[3][3], xb.y, wd3);
    }
    // halo xz values -> registers (x blocks only)
    float h1 = 0.f, h2 = 0.f;
    if (isx && l0 > 0) {
        {
            int j = tid >> 7, e = tid & 127;
            float a = sbc[e];
            for (int i = 0; i < 64; ++i)
                a = fmaf(sxn[i * 68 + 64 + j], swT[i * 132 + e], a);
            h1 = a;
        }
        if (tid < 128) {
            int e = tid;
            float a = sbc[e];
            for (int i = 0; i < 64; ++i)
                a = fmaf(sxn[i * 68 + 66], swT[i * 132 + e], a);
            h2 = a;
        }
    }
    __syncthreads();   // all reads of sxn/swT done -> reuse as stage
    #pragma unroll
    for (int p = 0; p < 4; ++p)
        #pragma unroll
        for (int j = 0; j < 4; ++j) {
            float2 v = upk(acc[p][j]);
            int e = (tx << 2) + j, t = ty * 8 + 2 * p;
            float bce = sbc[e];
            stage[e * 68 + 3 + t] = v.x + bce;
            stage[e * 68 + 4 + t] = v.y + bce;
        }
    if (isx) {
        { int j = tid >> 7, e = tid & 127; stage[e * 68 + j] = h1; }
        if (tid < 128) stage[tid * 68 + 2] = h2;
    }
    __syncthreads();
    if (isx) {
        for (int idx = tid; idx < 128 * 64; idx += 256) {
            int t = idx & 63, e = idx >> 6;
            int d = e0 + e;
            const float* st = &stage[e * 68];
            float4 w = *(const float4*)&cw[d * 4];
            float a = cb[d];
            a = fmaf(w.x, st[t], a);
            a = fmaf(w.y, st[t + 1], a);
            a = fmaf(w.z, st[t + 2], a);
            a = fmaf(w.w, st[t + 3], a);
            a = a / (1.f + __expf(-a));
            g_xc[(long)(b * DI + d) * LSEQ + l0 + t] = a;
        }
    } else {
        for (int idx = tid; idx < 128 * 64; idx += 256) {
            int t = idx & 63, e = idx >> 6;
            float v = stage[e * 68 + 3 + t];
            v = v / (1.f + __expf(-v));
            g_zs[(long)(b * DI + (e0 - DI) + e) * LSEQ + l0 + t] = v;
        }
    }
}

// ---------------- K4: x_dbl = x_proj @ x ; B,C ; delta (K-chunked, smem reuse) ---
__global__ void __launch_bounds__(256, 2)
k_xproj(const float* __restrict__ Xp, const float* __restrict__ Wdt,
        const float* __restrict__ bdt) {
    extern __shared__ float sm[];
    float* sdbl = sm;                 // 64*40 (persists)
    float* sxc  = sm + 2560;          // phase1: [t][kk] 64*132
    float* spc  = sm + 2560 + 8448;   // phase1: [e][kk] 40*132
    float* sdel = sm + 2560;          // phase2: [d][t] 256*65 (reuses chunk region)
    int tid = threadIdx.x;
    long t0 = (long)blockIdx.x * 64;
    int b = (int)(t0 >> 12);
    int l0 = (int)(t0 & (LSEQ - 1));

    int tt = tid >> 2, eb = (tid & 3) * 10;
    float acc[10] = {};
    for (int kc = 0; kc < 2; ++kc) {
        __syncthreads();
        for (int idx = tid; idx < 64 * 128; idx += 256) {
            int t = idx & 63, kk = idx >> 6;
            sxc[t * 132 + kk] = g_xc[(long)(b * DI + kc * 128 + kk) * LSEQ + l0 + t];
        }
        for (int idx = tid; idx < 40 * 128; idx += 256) {
            int kk = idx & 127, e = idx >> 7;
            spc[e * 132 + kk] = Xp[e * DI + kc * 128 + kk];
        }
        __syncthreads();
        for (int kk = 0; kk < 128; kk += 4) {
            float4 xv = *(const float4*)&sxc[tt * 132 + kk];
            #pragma unroll
            for (int e = 0; e < 10; ++e) {
                float4 wv = *(const float4*)&spc[(eb + e) * 132 + kk];
                acc[e] = fmaf(xv.x, wv.x, fmaf(xv.y, wv.y, fmaf(xv.z, wv.z, fmaf(xv.w, wv.w, acc[e]))));
            }
        }
    }
    __syncthreads();
    #pragma unroll
    for (int e = 0; e < 10; ++e) sdbl[tt * 40 + eb + e] = acc[e];
    __syncthreads();
    for (int idx = tid; idx < 64 * DS; idx += 256) {
        int t = idx >> 4, s = idx & 15;
        g_Bm[(t0 + t) * DS + s] = sdbl[t * 40 + 8 + s];
        g_Cm[(t0 + t) * DS + s] = sdbl[t * 40 + 24 + s];
    }
    {
        int d = tid;
        float wr[8];
        #pragma unroll
        for (int r = 0; r < 8; ++r) wr[r] = Wdt[d * 8 + r];
        float bb = bdt[d];
        for (int t = 0; t < 64; ++t) {
            float pre = bb;
            #pragma unroll
            for (int r = 0; r < 8; ++r) pre = fmaf(sdbl[t * 40 + r], wr[r], pre);
            float sp = (pre > 20.f) ? pre : log1pf(__expf(pre));
            sdel[d * 65 + t] = sp;
        }
    }
    __syncthreads();
    for (int idx = tid; idx < DI * 64; idx += 256) {
        int d = idx >> 6, t = idx & 63;
        g_delta[(long)(b * DI + d) * LSEQ + l0 + t] = sdel[d * 65 + t];
    }
}

// ---------------- K5a: per-chunk decay product P and local state q ----------------
__global__ void __launch_bounds__(256, 6)
k_scan1(const float* __restrict__ Alog) {
    int u = threadIdx.x >> 4;
    int s = threadIdx.x & 15;
    int unit = blockIdx.x * 16 + u;
    int g = unit & (NG - 1);
    int ch = unit >> 6;
    int b = ch >> 8, d = ch & 255;
    float Aval = -__expf(Alog[d * DS + s]);
    const float* pd = g_delta + (long)ch * LSEQ + g * CHK;
    const float* px = g_xc    + (long)ch * LSEQ + g * CHK;
    const float* pB = g_Bm    + ((long)b * LSEQ + g * CHK) * DS + s;
    float P = 1.f, q = 0.f;
    #pragma unroll 4
    for (int t = 0; t < CHK; t += 4) {
        float4 dv = *(const float4*)&pd[t];
        float4 xv = *(const float4*)&px[t];
        float B0 = pB[(t + 0) * DS], B1 = pB[(t + 1) * DS];
        float B2 = pB[(t + 2) * DS], B3 = pB[(t + 3) * DS];
        float a0 = __expf(dv.x * Aval); P *= a0; q = fmaf(a0, q, dv.x * xv.x * B0);
        float a1 = __expf(dv.y * Aval); P *= a1; q = fmaf(a1, q, dv.y * xv.y * B1);
        float a2 = __expf(dv.z * Aval); P *= a2; q = fmaf(a2, q, dv.z * xv.z * B2);
        float a3 = __expf(dv.w * Aval); P *= a3; q = fmaf(a3, q, dv.w * xv.w * B3);
    }
    long idx = (long)unit * DS + s;
    g_P[idx] = P;
    g_q[idx] = q;
}

// ---------------- K5b: propagate h_in across chunks ------------------------------
__global__ void k_scan2() {
    int tid = blockIdx.x * 256 + threadIdx.x;
    int ch = tid >> 4, s = tid & 15;
    float h = 0.f;
    long base = (long)ch * NG * DS + s;
    #pragma unroll 8
    for (int g = 0; g < NG; ++g) {
        long idx = base + (long)g * DS;
        g_hin[idx] = h;
        h = fmaf(g_P[idx], h, g_q[idx]);
    }
}

// ---------------- K5c: local scan from h_in, y = (C.h + x*D) * silu(z) -----------
__global__ void __launch_bounds__(256, 6)
k_scan3(const float* __restrict__ Alog, const float* __restrict__ Dp_) {
    __shared__ float ybuf[16 * CHK];
    int u = threadIdx.x >> 4;
    int s = threadIdx.x & 15;
    int unit = blockIdx.x * 16 + u;
    int g = unit & (NG - 1);
    int ch = unit >> 6;
    int b = ch >> 8, d = ch & 255;
    float Aval = -__expf(Alog[d * DS + s]);
    float Dp = Dp_[d];
    const float* pd = g_delta + (long)ch * LSEQ + g * CHK;
    const float* px = g_xc    + (long)ch * LSEQ + g * CHK;
    const float* pz = g_zs    + (long)ch * LSEQ + g * CHK;
    const float* pB = g_Bm    + ((long)b * LSEQ + g * CHK) * DS + s;
    const float* pC = g_Cm    + ((long)b * LSEQ + g * CHK) * DS + s;
    float h = g_hin[(long)unit * DS + s];
    #pragma unroll 2
    for (int t = 0; t < CHK; t += 4) {
        float4 dv = *(const float4*)&pd[t];
        float4 xv = *(const float4*)&px[t];
        float4 zv;
        if (s == 0) zv = *(const float4*)&pz[t];
        #pragma unroll
        for (int j = 0; j < 4; ++j) {
            float dvj = (j == 0) ? dv.x : (j == 1) ? dv.y : (j == 2) ? dv.z : dv.w;
            float xvj = (j == 0) ? xv.x : (j == 1) ? xv.y : (j == 2) ? xv.z : xv.w;
            float Bv = pB[(t + j) * DS];
            float Cv = pC[(t + j) * DS];
            float a = __expf(dvj * Aval);
            h = fmaf(a, h, dvj * xvj * Bv);
            float p = h * Cv;
            p += __shfl_xor_sync(0xffffffffu, p, 8);
            p += __shfl_xor_sync(0xffffffffu, p, 4);
            p += __shfl_xor_sync(0xffffffffu, p, 2);
            p += __shfl_xor_sync(0xffffffffu, p, 1);
            if (s == 0) {
                float zvj = (j == 0) ? zv.x : (j == 1) ? zv.y : (j == 2) ? zv.z : zv.w;
                ybuf[u * CHK + t + j] = (p + xvj * Dp) * zvj;
            }
        }
    }
    __syncthreads();
    float* py = g_y + (long)ch * LSEQ + (long)(blockIdx.x & 3) * 1024;
    for (int i = threadIdx.x; i < 16 * CHK; i += 256) py[i] = ybuf[i];
}

// ---------------- K6: m = rmsnorm2(mamba_out @ y) + u (K-chunked) ----------------
__global__ void __launch_bounds__(256, 4)
k_outproj(const float* __restrict__ Wmo, const float* __restrict__ wn2) {
    extern __shared__ float sm[];
    float* syT = sm;               // [k][t] 64*68 chunk
    float* swT = sm + 64 * 68;     // [k][o] 64*132 chunk
    int tid = threadIdx.x;
    long t0 = (long)blockIdx.x * 64;
    int b = (int)(t0 >> 12);
    int lpos = (int)(t0 & (LSEQ - 1));
    int tx = tid & 31, ty = tid >> 5;

    ull acc[4][4] = {};
    for (int kc = 0; kc < 4; ++kc) {
        __syncthreads();
        for (int idx = tid; idx < 64 * 64; idx += 256) {
            int t = idx & 63, k = idx >> 6;
            syT[k * 68 + t] = g_y[(long)(b * DI + kc * 64 + k) * LSEQ + lpos + t];
        }
        for (int idx = tid; idx < 64 * DM; idx += 256) {
            int k = idx & 63, o = idx >> 6;
            swT[k * 132 + o] = Wmo[(long)o * DI + kc * 64 + k];
        }
        __syncthreads();
        for (int k = 0; k < 64; ++k) {
            float4 w4 = *(const float4*)&swT[k * 132 + (tx << 2)];
            ull wd0 = pk2(w4.x, w4.x), wd1 = pk2(w4.y, w4.y);
            ull wd2 = pk2(w4.z, w4.z), wd3 = pk2(w4.w, w4.w);
            ulonglong2 xa = *(const ulonglong2*)&syT[k * 68 + ty * 8];
            ulonglong2 xb = *(const ulonglong2*)&syT[k * 68 + ty * 8 + 4];
            fma2(acc[0][0], xa.x, wd0); fma2(acc[0][1], xa.x, wd1); fma2(acc[0][2], xa.x, wd2); fma2(acc[0][3], xa.x, wd3);
            fma2(acc[1][0], xa.y, wd0); fma2(acc[1][1], xa.y, wd1); fma2(acc[1][2], xa.y, wd2); fma2(acc[1][3], xa.y, wd3);
            fma2(acc[2][0], xb.x, wd0); fma2(acc[2][1], xb.x, wd1); fma2(acc[2][2], xb.x, wd2); fma2(acc[2][3], xb.x, wd3);
            fma2(acc[3][0], xb.y, wd0); fma2(acc[3][1], xb.y, wd1); fma2(acc[3][2], xb.y, wd2); fma2(acc[3][3], xb.y, wd3);
        }
    }
    float af[8][4];
    #pragma unroll
    for (int p = 0; p < 4; ++p)
        #pragma unroll
        for (int j = 0; j < 4; ++j) {
            float2 v = upk(acc[p][j]);
            af[2 * p][j] = v.x;
            af[2 * p + 1][j] = v.y;
        }
    float4 w2q = *(const float4*)&wn2[tx << 2];
    #pragma unroll
    for (int r = 0; r < 8; ++r) {
        float ss = 0.f;
        #pragma unroll
        for (int j = 0; j < 4; ++j) ss = fmaf(af[r][j], af[r][j], ss);
        #pragma unroll
        for (int off = 16; off >= 1; off >>= 1) ss += __shfl_xor_sync(0xffffffffu, ss, off);
        float sc = rsqrtf(ss * (1.f / DM) + 1e-5f);
        long t = t0 + ty * 8 + r;
        float4 uq = *(const float4*)&g_u[t * DM + (tx << 2)];
        float4 ov = make_float4(af[r][0] * sc * w2q.x + uq.x,
                                af[r][1] * sc * w2q.y + uq.y,
                                af[r][2] * sc * w2q.z + uq.z,
                                af[r][3] * sc * w2q.w + uq.w);
        *(float4*)&g_m[t * DM + (tx << 2)] = ov;
    }
}

// ---------------- K7: w = swish(W_wp@xn+b) ; out = W_op@(w*m)+b + x ---------------
__global__ void __launch_bounds__(256, 2)
k_final(const float* __restrict__ Wwp, const float* __restrict__ bwp,
        const float* __restrict__ Wop, const float* __restrict__ bop,
        const float* __restrict__ x, float* __restrict__ out) {
    extern __shared__ float sm[];
    float* smm  = sm;                      // [t][c] 64*132 (persists)
    float* sxn  = sm + 64 * 132;           // [i][t] 64*68 (phase 1)
    float* swpT = sm + 64 * 132 + 64 * 68; // [i][c] 64*132 (phase 1)
    float* sopT = sm + 64 * 132;           // [c][o] 128*68 (phase 2, reuse)
    int tid = threadIdx.x;
    long t0 = (long)blockIdx.x * 64;

    for (int idx = tid; idx < 64 * DM; idx += 256) {
        int c = idx & 127, t = idx >> 7;
        smm[t * 132 + c] = g_m[(t0 + t) * DM + c];
    }
    for (int idx = tid; idx < 64 * 64; idx += 256) {
        int i = idx & 63, t = idx >> 6;
        sxn[i * 68 + t] = g_xn[(t0 + t) * DMO + i];
    }
    for (int idx = tid; idx < DM * DMO; idx += 256) {
        int i = idx & 63, c = idx >> 6;
        swpT[i * 132 + c] = Wwp[c * DMO + i];
    }
    __syncthreads();
    int tx = tid & 31, ty = tid >> 5;
    {
        ull acc[4][4] = {};
        for (int i = 0; i < DMO; ++i) {
            float4 w4 = *(const float4*)&swpT[i * 132 + (tx << 2)];
            ull wd0 = pk2(w4.x, w4.x), wd1 = pk2(w4.y, w4.y);
            ull wd2 = pk2(w4.z, w4.z), wd3 = pk2(w4.w, w4.w);
            ulonglong2 xa = *(const ulonglong2*)&sxn[i * 68 + ty * 8];
            ulonglong2 xb = *(const ulonglong2*)&sxn[i * 68 + ty * 8 + 4];
            fma2(acc[0][0], xa.x, wd0); fma2(acc[0][1], xa.x, wd1); fma2(acc[0][2], xa.x, wd2); fma2(acc[0][3], xa.x, wd3);
            fma2(acc[1][0], xa.y, wd0); fma2(acc[1][1], xa.y, wd1); fma2(acc[1][2], xa.y, wd2); fma2(acc[1][3], xa.y, wd3);
            fma2(acc[2][0], xb.x, wd0); fma2(acc[2][1], xb.x, wd1); fma2(acc[2][2], xb.x, wd2); fma2(acc[2][3], xb.x, wd3);
            fma2(acc[3][0], xb.y, wd0); fma2(acc[3][1], xb.y, wd1); fma2(acc[3][2], xb.y, wd2); fma2(acc[3][3], xb.y, wd3);
        }
        float4 bq = *(const float4*)&bwp[tx << 2];
        float bj[4] = {bq.x, bq.y, bq.z, bq.w};
        #pragma unroll
        for (int p = 0; p < 4; ++p)
            #pragma unroll
            for (int j = 0; j < 4; ++j) {
                float2 v = upk(acc[p][j]);
                int c = (tx << 2) + j;
                int ta = ty * 8 + 2 * p;
                float va = v.x + bj[j], vb = v.y + bj[j];
                float wa = va / (1.f + __expf(-va));
                float wb = vb / (1.f + __expf(-vb));
                smm[ta * 132 + c] *= wa;
                smm[(ta + 1) * 132 + c] *= wb;
            }
    }
    __syncthreads();   // sxn/swpT dead -> load sopT
    for (int idx = tid; idx < DMO * DM; idx += 256) {
        int c = idx & 127, o = idx >> 7;
        sopT[c * 68 + o] = Wop[o * DM + c];
    }
    __syncthreads();
    {
        int rowg = tid >> 4;
        int o4 = (tid & 15) << 2;
        float a2[4][4] = {};
        for (int c = 0; c < DM; c += 4) {
            float4 q0 = *(const float4*)&sopT[(c + 0) * 68 + o4];
            float4 q1 = *(const float4*)&sopT[(c + 1) * 68 + o4];
            float4 q2 = *(const float4*)&sopT[(c + 2) * 68 + o4];
            float4 q3 = *(const float4*)&sopT[(c + 3) * 68 + o4];
            #pragma unroll
            for (int rr = 0; rr < 4; ++rr) {
                float4 pv = *(const float4*)&smm[(rowg * 4 + rr) * 132 + c];
                a2[rr][0] = fmaf(pv.x, q0.x, fmaf(pv.y, q1.x, fmaf(pv.z, q2.x, fmaf(pv.w, q3.x, a2[rr][0]))));
                a2[rr][1] = fmaf(pv.x, q0.y, fmaf(pv.y, q1.y, fmaf(pv.z, q2.y, fmaf(pv.w, q3.y, a2[rr][1]))));
                a2[rr][2] = fmaf(pv.x, q0.z, fmaf(pv.y, q1.z, fmaf(pv.z, q2.z, fmaf(pv.w, q3.z, a2[rr][2]))));
                a2[rr][3] = fmaf(pv.x, q0.w, fmaf(pv.y, q1.w, fmaf(pv.z, q2.w, fmaf(pv.w, q3.w, a2[rr][3]))));
            }
        }
        float4 bq = *(const float4*)&bop[o4];
        #pragma unroll
        for (int rr = 0; rr < 4; ++rr) {
            long tg = t0 + rowg * 4 + rr;
            float4 xq = *(const float4*)&x[tg * DMO + o4];
            float4 ov = make_float4(a2[rr][0] + bq.x + xq.x, a2[rr][1] + bq.y + xq.y,
                                    a2[rr][2] + bq.z + xq.z, a2[rr][3] + bq.w + xq.w);
            *(float4*)&out[tg * DMO + o4] = ov;
        }
    }
}

// ---------------- launch -----------------------------------------------------------
extern "C" void kernel_launch(void* const* d_in, const int* in_sizes, int n_in,
                              void* d_out, int out_size) {
    const float* x    = (const float*)d_in[0];
    const float* wn1  = (const float*)d_in[1];
    const float* wn2  = (const float*)d_in[2];
    const float* Wip  = (const float*)d_in[3];
    const float* bip  = (const float*)d_in[4];
    const float* Wfp  = (const float*)d_in[5];
    const float* bfp  = (const float*)d_in[6];
    const float* Wwp  = (const float*)d_in[7];
    const float* bwp  = (const float*)d_in[8];
    const float* Wop  = (const float*)d_in[9];
    const float* bop  = (const float*)d_in[10];
    const float* Win  = (const float*)d_in[11];
    const float* cw   = (const float*)d_in[12];
    const float* cb   = (const float*)d_in[13];
    const float* Xp   = (const float*)d_in[14];
    const float* Wdt  = (const float*)d_in[15];
    const float* bdt  = (const float*)d_in[16];
    const float* Alog = (const float*)d_in[17];
    const float* Dpar = (const float*)d_in[18];
    const float* Wmo  = (const float*)d_in[19];
    float* out = (float*)d_out;

    const int SM_K1 = (64 * 68 + 64 * 132 + 64) * 4;
    const int SM_K2 = (12800 + 128) * 4;
    const int SM_K4 = (2560 + 256 * 65) * 4;
    const int SM_K6 = (64 * 68 + 64 * 132) * 4;
    const int SM_K7 = (64 * 132 + 64 * 68 + 64 * 132) * 4;

    cudaFuncSetAttribute(k_rms_u,   cudaFuncAttributeMaxDynamicSharedMemorySize, SM_K1);
    cudaFuncSetAttribute(k_inproj,  cudaFuncAttributeMaxDynamicSharedMemorySize, SM_K2);
    cudaFuncSetAttribute(k_xproj,   cudaFuncAttributeMaxDynamicSharedMemorySize, SM_K4);
    cudaFuncSetAttribute(k_outproj, cudaFuncAttributeMaxDynamicSharedMemorySize, SM_K6);
    cudaFuncSetAttribute(k_final,   cudaFuncAttributeMaxDynamicSharedMemorySize, SM_K7);

    k_combine<<<32, 256>>>(Wfp, Wip, bip, bfp);
    k_combine2<<<128, 256>>>(Win);
    k_rms_u<<<TOK / 64, 256, SM_K1>>>(x, wn1);
    k_inproj<<<dim3(TOK / 64, 4), 256, SM_K2>>>(cw, cb);
    k_xproj<<<TOK / 64, 256, SM_K4>>>(Xp, Wdt, bdt);
    k_scan1<<<NUNIT / 16, 256>>>(Alog);
    k_scan2<<<64, 256>>>();
    k_scan3<<<NUNIT / 16, 256>>>(Alog, Dpar);
    k_outproj<<<TOK / 64, 256, SM_K6>>>(Wmo, wn2);
    k_final<<<TOK / 64, 256, SM_K7>>>(Wwp, bwp, Wop, bop, x, out);
}

// round 9
// speedup vs baseline: 1.9082x; 1.0122x over previous
#include <cuda_runtime.h>

#define TOK 16384
#define LSEQ 4096
#define NB 4
#define DMO 64      // input/output dim D
#define DM 128      // d_model of mamba (2D)
#define DI 256      // d_inner
#define DS 16       // d_state
#define DTR 8       // dt_rank
#define NCH 1024    // NB * DI channels
#define CHK 64      // chunk length
#define NG (LSEQ / CHK)   // 64 chunks
#define NUNIT (NCH * NG)  // 65536 units

typedef unsigned long long ull;

__device__ __forceinline__ ull pk2(float a, float b) {
    ull r; asm("mov.b64 %0, {%1, %2};" : "=l"(r) : "f"(a), "f"(b)); return r;
}
__device__ __forceinline__ void fma2(ull& d, ull a, ull b) {
    asm("fma.rn.f32x2 %0, %1, %2, %3;" : "=l"(d) : "l"(a), "l"(b), "l"(d));
}
__device__ __forceinline__ float2 upk(ull v) {
    float2 r; asm("mov.b64 {%0, %1}, %2;" : "=f"(r.x), "=f"(r.y) : "l"(v)); return r;
}

// 16 packed FMAs: 4 tokens-pairs x 4 outputs
#define FMA16(acc, x0, x1, x2, x3, wd0, wd1, wd2, wd3) \
    fma2(acc[0][0], x0, wd0); fma2(acc[0][1], x0, wd1); fma2(acc[0][2], x0, wd2); fma2(acc[0][3], x0, wd3); \
    fma2(acc[1][0], x1, wd0); fma2(acc[1][1], x1, wd1); fma2(acc[1][2], x1, wd2); fma2(acc[1][3], x1, wd3); \
    fma2(acc[2][0], x2, wd0); fma2(acc[2][1], x2, wd1); fma2(acc[2][2], x2, wd2); fma2(acc[2][3], x2, wd3); \
    fma2(acc[3][0], x3, wd0); fma2(acc[3][1], x3, wd1); fma2(acc[3][2], x3, wd2); fma2(acc[3][3], x3, wd3)

// ---------------- scratch ----------------
// xc / zs / delta / y are CHANNEL-MAJOR: [(b*DI + d) * LSEQ + l]
__device__ float g_Wu[DM * DMO];      // W_fp @ W_ip
__device__ float g_bu[DM];            // W_fp @ b_ip + b_fp
__device__ float g_Wc[2 * DI * DMO];  // in_proj @ W_u   (512 x 64)
__device__ float g_bc[2 * DI];        // in_proj @ b_u
__device__ float g_xn[TOK * DMO];
__device__ float g_u[TOK * DM];
__device__ float g_xc[NCH * LSEQ];
__device__ float g_zs[NCH * LSEQ];
__device__ float g_delta[NCH * LSEQ];
__device__ float g_Bm[TOK * DS];
__device__ float g_Cm[TOK * DS];
__device__ float g_y[NCH * LSEQ];
__device__ float g_m[TOK * DM];
__device__ float g_P[NUNIT * DS];
__device__ float g_q[NUNIT * DS];
__device__ float g_hin[NUNIT * DS];

// ---------------- K0: compose W_u = W_fp @ W_ip, b_u = W_fp@b_ip + b_fp ----------
__global__ void k_combine(const float* __restrict__ Wfp, const float* __restrict__ Wip,
                          const float* __restrict__ bip, const float* __restrict__ bfp) {
    int idx = blockIdx.x * 256 + threadIdx.x;
    int o = idx / DMO, i = idx % DMO;
    float s = 0.f;
    for (int k = 0; k < DM; ++k) s = fmaf(Wfp[o * DM + k], Wip[k * DMO + i], s);
    g_Wu[idx] = s;
    if (blockIdx.x == 0 && threadIdx.x < DM) {
        int t = threadIdx.x;
        float sb = bfp[t];
        for (int k = 0; k < DM; ++k) sb = fmaf(Wfp[t * DM + k], bip[k], sb);
        g_bu[t] = sb;
    }
}

// ---------------- K0b: compose W_c = in_proj @ W_u, b_c = in_proj @ b_u ----------
__global__ void k_combine2(const float* __restrict__ Win) {
    int idx = blockIdx.x * 256 + threadIdx.x;   // 128 blocks -> 32768 = 512*64
    int e = idx >> 6, i = idx & 63;
    float s = 0.f;
    for (int k = 0; k < DM; ++k) s = fmaf(Win[(long)e * DM + k], g_Wu[k * DMO + i], s);
    g_Wc[idx] = s;
    if (i == 0) {
        float sb = 0.f;
        for (int k = 0; k < DM; ++k) sb = fmaf(Win[(long)e * DM + k], g_bu[k], sb);
        g_bc[e] = sb;
    }
}

// ---------------- K1: rmsnorm1 + u = W_u @ xn + b_u ------------------------------
__global__ void __launch_bounds__(256, 3)
k_rms_u(const float* __restrict__ x, const float* __restrict__ wn1) {
    extern __shared__ float sm[];
    float* sx  = sm;                 // 64*68 [i][t]
    float* swT = sm + 64 * 68;       // 64*132 [i][o]  (+pad row for prefetch)
    float* ssc = swT + 65 * 132;     // 64
    int tid = threadIdx.x;
    long t0 = (long)blockIdx.x * 64;

    for (int idx = tid; idx < 64 * 64; idx += 256) {
        int i = idx & 63, t = idx >> 6;
        sx[i * 68 + t] = x[(t0 + t) * DMO + i];
    }
    for (int idx = tid; idx < DM * DMO; idx += 256) {
        int i = idx & 63, o = idx >> 6;
        swT[i * 132 + o] = g_Wu[o * DMO + i];
    }
    __syncthreads();
    if (tid < 64) {
        float ss = 0.f;
        for (int i = 0; i < DMO; ++i) { float v = sx[i * 68 + tid]; ss = fmaf(v, v, ss); }
        ssc[tid] = rsqrtf(ss * (1.f / DMO) + 1e-5f);
    }
    __syncthreads();
    for (int idx = tid; idx < 64 * 64; idx += 256) {
        int i = idx & 63, t = idx >> 6;
        float v = sx[i * 68 + t] * ssc[t] * wn1[i];
        sx[i * 68 + t] = v;
        g_xn[(t0 + t) * DMO + i] = v;
    }
    __syncthreads();
    int tx = tid & 31, ty = tid >> 5;
    ull acc[4][4] = {};
    float4 w4 = *(const float4*)&swT[tx << 2];
    ulonglong2 xa = *(const ulonglong2*)&sx[ty * 8];
    ulonglong2 xb = *(const ulonglong2*)&sx[ty * 8 + 4];
    #pragma unroll 8
    for (int i = 0; i < DMO; ++i) {
        ull wd0 = pk2(w4.x, w4.x), wd1 = pk2(w4.y, w4.y);
        ull wd2 = pk2(w4.z, w4.z), wd3 = pk2(w4.w, w4.w);
        ull x0 = xa.x, x1 = xa.y, x2 = xb.x, x3 = xb.y;
        w4 = *(const float4*)&swT[(i + 1) * 132 + (tx << 2)];
        xa = *(const ulonglong2*)&sx[(i + 1) * 68 + ty * 8];
        xb = *(const ulonglong2*)&sx[(i + 1) * 68 + ty * 8 + 4];
        FMA16(acc, x0, x1, x2, x3, wd0, wd1, wd2, wd3);
    }
    float4 bq = *(const float4*)&g_bu[tx << 2];
    #pragma unroll
    for (int p = 0; p < 4; ++p) {
        float2 v0 = upk(acc[p][0]), v1 = upk(acc[p][1]), v2 = upk(acc[p][2]), v3 = upk(acc[p][3]);
        long ta = t0 + ty * 8 + 2 * p, tb = ta + 1;
        float4 lo = make_float4(v0.x + bq.x, v1.x + bq.y, v2.x + bq.z, v3.x + bq.w);
        float4 hi = make_float4(v0.y + bq.x, v1.y + bq.y, v2.y + bq.z, v3.y + bq.w);
        *(float4*)&g_u[ta * DM + (tx << 2)] = lo;
        *(float4*)&g_u[tb * DM + (tx << 2)] = hi;
    }
}

// ---------------- K2: xz = W_c @ xn + b_c ; fused conv+silu (x) / silu (z) --------
__global__ void __launch_bounds__(256, 3)
k_inproj(const float* __restrict__ cw, const float* __restrict__ cb) {
    extern __shared__ float sm[];
    float* sxn   = sm;                 // [i][t] 64*68 ; cols 0-63 main, 64-66 halo
    float* swT   = sm + 64 * 68;       // [i][e] 64*132 (+pad for prefetch)
    float* sbc   = sm + 12800 + 140;   // 128 biases (persists)
    float* stage = sm;                 // [e][t'] 128*68 AFTER GEMM (reuse)
    int tid = threadIdx.x;
    long t0 = (long)blockIdx.x * 64;
    int e0 = blockIdx.y * 128;
    int b = (int)(t0 >> 12);
    int l0 = (int)(t0 & (LSEQ - 1));
    bool isx = (e0 < DI);

    for (int idx = tid; idx < 64 * 64; idx += 256) {
        int i = idx & 63, t = idx >> 6;
        sxn[i * 68 + t] = g_xn[(t0 + t) * DMO + i];
    }
    for (int idx = tid; idx < 128 * 64; idx += 256) {
        int i = idx & 63, e = idx >> 6;
        swT[i * 132 + e] = g_Wc[(long)(e0 + e) * DMO + i];
    }
    if (tid < 128) sbc[tid] = g_bc[e0 + tid];
    if (isx && tid < 192) {   // halo xn: tokens t0-3..t0-1
        int i = tid & 63, j = tid >> 6;
        sxn[i * 68 + 64 + j] = (l0 > 0) ? g_xn[(t0 - 3 + j) * DMO + i] : 0.f;
    }
    __syncthreads();
    int tx = tid & 31, ty = tid >> 5;
    ull acc[4][4] = {};
    {
        float4 w4 = *(const float4*)&swT[tx << 2];
        ulonglong2 xa = *(const ulonglong2*)&sxn[ty * 8];
        ulonglong2 xb = *(const ulonglong2*)&sxn[ty * 8 + 4];
        #pragma unroll 8
        for (int i = 0; i < 64; ++i) {
            ull wd0 = pk2(w4.x, w4.x), wd1 = pk2(w4.y, w4.y);
            ull wd2 = pk2(w4.z, w4.z), wd3 = pk2(w4.w, w4.w);
            ull x0 = xa.x, x1 = xa.y, x2 = xb.x, x3 = xb.y;
            w4 = *(const float4*)&swT[(i + 1) * 132 + (tx << 2)];
            xa = *(const ulonglong2*)&sxn[(i + 1) * 68 + ty * 8];
            xb = *(const ulonglong2*)&sxn[(i + 1) * 68 + ty * 8 + 4];
            FMA16(acc, x0, x1, x2, x3, wd0, wd1, wd2, wd3);
        }
    }
    // halo xz values -> registers (x blocks only)
    float h1 = 0.f, h2 = 0.f;
    if (isx && l0 > 0) {
        {
            int j = tid >> 7, e = tid & 127;
            float a = sbc[e];
            for (int i = 0; i < 64; ++i)
                a = fmaf(sxn[i * 68 + 64 + j], swT[i * 132 + e], a);
            h1 = a;
        }
        if (tid < 128) {
            int e = tid;
            float a = sbc[e];
            for (int i = 0; i < 64; ++i)
                a = fmaf(sxn[i * 68 + 66], swT[i * 132 + e], a);
            h2 = a;
        }
    }
    __syncthreads();   // all reads of sxn/swT done -> reuse as stage
    #pragma unroll
    for (int p = 0; p < 4; ++p)
        #pragma unroll
        for (int j = 0; j < 4; ++j) {
            float2 v = upk(acc[p][j]);
            int e = (tx << 2) + j, t = ty * 8 + 2 * p;
            float bce = sbc[e];
            stage[e * 68 + 3 + t] = v.x + bce;
            stage[e * 68 + 4 + t] = v.y + bce;
        }
    if (isx) {
        { int j = tid >> 7, e = tid & 127; stage[e * 68 + j] = h1; }
        if (tid < 128) stage[tid * 68 + 2] = h2;
    }
    __syncthreads();
    if (isx) {
        for (int idx = tid; idx < 128 * 64; idx += 256) {
            int t = idx & 63, e = idx >> 6;
            int d = e0 + e;
            const float* st = &stage[e * 68];
            float4 w = *(const float4*)&cw[d * 4];
            float a = cb[d];
            a = fmaf(w.x, st[t], a);
            a = fmaf(w.y, st[t + 1], a);
            a = fmaf(w.z, st[t + 2], a);
            a = fmaf(w.w, st[t + 3], a);
            a = a / (1.f + __expf(-a));
            g_xc[(long)(b * DI + d) * LSEQ + l0 + t] = a;
        }
    } else {
        for (int idx = tid; idx < 128 * 64; idx += 256) {
            int t = idx & 63, e = idx >> 6;
            float v = stage[e * 68 + 3 + t];
            v = v / (1.f + __expf(-v));
            g_zs[(long)(b * DI + (e0 - DI) + e) * LSEQ + l0 + t] = v;
        }
    }
}

// ---------------- K4: x_dbl = x_proj @ x ; B,C ; delta (K-chunked, smem reuse) ---
__global__ void __launch_bounds__(256, 2)
k_xproj(const float* __restrict__ Xp, const float* __restrict__ Wdt,
        const float* __restrict__ bdt) {
    extern __shared__ float sm[];
    float* sdbl = sm;                 // 64*40 (persists)
    float* sxc  = sm + 2560;          // phase1: [t][kk] 64*132
    float* spc  = sm + 2560 + 8448;   // phase1: [e][kk] 40*132
    float* sdel = sm + 2560;          // phase2: [d][t] 256*65 (reuses chunk region)
    int tid = threadIdx.x;
    long t0 = (long)blockIdx.x * 64;
    int b = (int)(t0 >> 12);
    int l0 = (int)(t0 & (LSEQ - 1));

    int tt = tid >> 2, eb = (tid & 3) * 10;
    float acc[10] = {};
    for (int kc = 0; kc < 2; ++kc) {
        __syncthreads();
        for (int idx = tid; idx < 64 * 128; idx += 256) {
            int t = idx & 63, kk = idx >> 6;
            sxc[t * 132 + kk] = g_xc[(long)(b * DI + kc * 128 + kk) * LSEQ + l0 + t];
        }
        for (int idx = tid; idx < 40 * 128; idx += 256) {
            int kk = idx & 127, e = idx >> 7;
            spc[e * 132 + kk] = Xp[e * DI + kc * 128 + kk];
        }
        __syncthreads();
        for (int kk = 0; kk < 128; kk += 4) {
            float4 xv = *(const float4*)&sxc[tt * 132 + kk];
            #pragma unroll
            for (int e = 0; e < 10; ++e) {
                float4 wv = *(const float4*)&spc[(eb + e) * 132 + kk];
                acc[e] = fmaf(xv.x, wv.x, fmaf(xv.y, wv.y, fmaf(xv.z, wv.z, fmaf(xv.w, wv.w, acc[e]))));
            }
        }
    }
    __syncthreads();
    #pragma unroll
    for (int e = 0; e < 10; ++e) sdbl[tt * 40 + eb + e] = acc[e];
    __syncthreads();
    for (int idx = tid; idx < 64 * DS; idx += 256) {
        int t = idx >> 4, s = idx & 15;
        g_Bm[(t0 + t) * DS + s] = sdbl[t * 40 + 8 + s];
        g_Cm[(t0 + t) * DS + s] = sdbl[t * 40 + 24 + s];
    }
    {
        int d = tid;
        float wr[8];
        #pragma unroll
        for (int r = 0; r < 8; ++r) wr[r] = Wdt[d * 8 + r];
        float bb = bdt[d];
        for (int t = 0; t < 64; ++t) {
            float pre = bb;
            #pragma unroll
            for (int r = 0; r < 8; ++r) pre = fmaf(sdbl[t * 40 + r], wr[r], pre);
            float sp = (pre > 20.f) ? pre : log1pf(__expf(pre));
            sdel[d * 65 + t] = sp;
        }
    }
    __syncthreads();
    for (int idx = tid; idx < DI * 64; idx += 256) {
        int d = idx >> 6, t = idx & 63;
        g_delta[(long)(b * DI + d) * LSEQ + l0 + t] = sdel[d * 65 + t];
    }
}

// ---------------- K5a: per-chunk decay product P and local state q ----------------
__global__ void __launch_bounds__(256, 6)
k_scan1(const float* __restrict__ Alog) {
    int u = threadIdx.x >> 4;
    int s = threadIdx.x & 15;
    int unit = blockIdx.x * 16 + u;
    int g = unit & (NG - 1);
    int ch = unit >> 6;
    int b = ch >> 8, d = ch & 255;
    float Aval = -__expf(Alog[d * DS + s]);
    const float* pd = g_delta + (long)ch * LSEQ + g * CHK;
    const float* px = g_xc    + (long)ch * LSEQ + g * CHK;
    const float* pB = g_Bm    + ((long)b * LSEQ + g * CHK) * DS + s;
    float P = 1.f, q = 0.f;
    #pragma unroll 4
    for (int t = 0; t < CHK; t += 4) {
        float4 dv = *(const float4*)&pd[t];
        float4 xv = *(const float4*)&px[t];
        float B0 = pB[(t + 0) * DS], B1 = pB[(t + 1) * DS];
        float B2 = pB[(t + 2) * DS], B3 = pB[(t + 3) * DS];
        float a0 = __expf(dv.x * Aval); P *= a0; q = fmaf(a0, q, dv.x * xv.x * B0);
        float a1 = __expf(dv.y * Aval); P *= a1; q = fmaf(a1, q, dv.y * xv.y * B1);
        float a2 = __expf(dv.z * Aval); P *= a2; q = fmaf(a2, q, dv.z * xv.z * B2);
        float a3 = __expf(dv.w * Aval); P *= a3; q = fmaf(a3, q, dv.w * xv.w * B3);
    }
    long idx = (long)unit * DS + s;
    g_P[idx] = P;
    g_q[idx] = q;
}

// ---------------- K5b: propagate h_in across chunks ------------------------------
__global__ void k_scan2() {
    int tid = blockIdx.x * 256 + threadIdx.x;
    int ch = tid >> 4, s = tid & 15;
    float h = 0.f;
    long base = (long)ch * NG * DS + s;
    #pragma unroll 8
    for (int g = 0; g < NG; ++g) {
        long idx = base + (long)g * DS;
        g_hin[idx] = h;
        h = fmaf(g_P[idx], h, g_q[idx]);
    }
}

// ---------------- K5c: local scan from h_in, y = (C.h + x*D) * silu(z) -----------
__global__ void __launch_bounds__(256, 6)
k_scan3(const float* __restrict__ Alog, const float* __restrict__ Dp_) {
    __shared__ float ybuf[16 * CHK];
    int u = threadIdx.x >> 4;
    int s = threadIdx.x & 15;
    int unit = blockIdx.x * 16 + u;
    int g = unit & (NG - 1);
    int ch = unit >> 6;
    int b = ch >> 8, d = ch & 255;
    float Aval = -__expf(Alog[d * DS + s]);
    float Dp = Dp_[d];
    const float* pd = g_delta + (long)ch * LSEQ + g * CHK;
    const float* px = g_xc    + (long)ch * LSEQ + g * CHK;
    const float* pz = g_zs    + (long)ch * LSEQ + g * CHK;
    const float* pB = g_Bm    + ((long)b * LSEQ + g * CHK) * DS + s;
    const float* pC = g_Cm    + ((long)b * LSEQ + g * CHK) * DS + s;
    float h = g_hin[(long)unit * DS + s];
    #pragma unroll 2
    for (int t = 0; t < CHK; t += 4) {
        float4 dv = *(const float4*)&pd[t];
        float4 xv = *(const float4*)&px[t];
        float4 zv;
        if (s == 0) zv = *(const float4*)&pz[t];
        #pragma unroll
        for (int j = 0; j < 4; ++j) {
            float dvj = (j == 0) ? dv.x : (j == 1) ? dv.y : (j == 2) ? dv.z : dv.w;
            float xvj = (j == 0) ? xv.x : (j == 1) ? xv.y : (j == 2) ? xv.z : xv.w;
            float Bv = pB[(t + j) * DS];
            float Cv = pC[(t + j) * DS];
            float a = __expf(dvj * Aval);
            h = fmaf(a, h, dvj * xvj * Bv);
            float p = h * Cv;
            p += __shfl_xor_sync(0xffffffffu, p, 8);
            p += __shfl_xor_sync(0xffffffffu, p, 4);
            p += __shfl_xor_sync(0xffffffffu, p, 2);
            p += __shfl_xor_sync(0xffffffffu, p, 1);
            if (s == 0) {
                float zvj = (j == 0) ? zv.x : (j == 1) ? zv.y : (j == 2) ? zv.z : zv.w;
                ybuf[u * CHK + t + j] = (p + xvj * Dp) * zvj;
            }
        }
    }
    __syncthreads();
    float* py = g_y + (long)ch * LSEQ + (long)(blockIdx.x & 3) * 1024;
    for (int i = threadIdx.x; i < 16 * CHK; i += 256) py[i] = ybuf[i];
}

// ---------------- K6: m = rmsnorm2(mamba_out @ y) + u (K-chunked) ----------------
__global__ void __launch_bounds__(256, 3)
k_outproj(const float* __restrict__ Wmo, const float* __restrict__ wn2) {
    extern __shared__ float sm[];
    float* syT = sm;               // [k][t] 64*68 chunk
    float* swT = sm + 64 * 68;     // [k][o] 64*132 chunk (+pad for prefetch)
    int tid = threadIdx.x;
    long t0 = (long)blockIdx.x * 64;
    int b = (int)(t0 >> 12);
    int lpos = (int)(t0 & (LSEQ - 1));
    int tx = tid & 31, ty = tid >> 5;

    ull acc[4][4] = {};
    for (int kc = 0; kc < 4; ++kc) {
        __syncthreads();
        for (int idx = tid; idx < 64 * 16; idx += 256) {
            int t4 = idx & 15, k = idx >> 4;
            *(float4*)&syT[k * 68 + t4 * 4] =
                *(const float4*)&g_y[(long)(b * DI + kc * 64 + k) * LSEQ + lpos + t4 * 4];
        }
        for (int idx = tid; idx < 64 * DM; idx += 256) {
            int k = idx & 63, o = idx >> 6;
            swT[k * 132 + o] = Wmo[(long)o * DI + kc * 64 + k];
        }
        __syncthreads();
        float4 w4 = *(const float4*)&swT[tx << 2];
        ulonglong2 xa = *(const ulonglong2*)&syT[ty * 8];
        ulonglong2 xb = *(const ulonglong2*)&syT[ty * 8 + 4];
        #pragma unroll 8
        for (int k = 0; k < 64; ++k) {
            ull wd0 = pk2(w4.x, w4.x), wd1 = pk2(w4.y, w4.y);
            ull wd2 = pk2(w4.z, w4.z), wd3 = pk2(w4.w, w4.w);
            ull x0 = xa.x, x1 = xa.y, x2 = xb.x, x3 = xb.y;
            w4 = *(const float4*)&swT[(k + 1) * 132 + (tx << 2)];
            xa = *(const ulonglong2*)&syT[(k + 1) * 68 + ty * 8];
            xb = *(const ulonglong2*)&syT[(k + 1) * 68 + ty * 8 + 4];
            FMA16(acc, x0, x1, x2, x3, wd0, wd1, wd2, wd3);
        }
    }
    float af[8][4];
    #pragma unroll
    for (int p = 0; p < 4; ++p)
        #pragma unroll
        for (int j = 0; j < 4; ++j) {
            float2 v = upk(acc[p][j]);
            af[2 * p][j] = v.x;
            af[2 * p + 1][j] = v.y;
        }
    float4 w2q = *(const float4*)&wn2[tx << 2];
    #pragma unroll
    for (int r = 0; r < 8; ++r) {
        float ss = 0.f;
        #pragma unroll
        for (int j = 0; j < 4; ++j) ss = fmaf(af[r][j], af[r][j], ss);
        #pragma unroll
        for (int off = 16; off >= 1; off >>= 1) ss += __shfl_xor_sync(0xffffffffu, ss, off);
        float sc = rsqrtf(ss * (1.f / DM) + 1e-5f);
        long t = t0 + ty * 8 + r;
        float4 uq = *(const float4*)&g_u[t * DM + (tx << 2)];
        float4 ov = make_float4(af[r][0] * sc * w2q.x + uq.x,
                                af[r][1] * sc * w2q.y + uq.y,
                                af[r][2] * sc * w2q.z + uq.z,
                                af[r][3] * sc * w2q.w + uq.w);
        *(float4*)&g_m[t * DM + (tx << 2)] = ov;
    }
}

// ---------------- K7: w = swish(W_wp@xn+b) ; out = W_op@(w*m)+b + x ---------------
__global__ void __launch_bounds__(256, 2)
k_final(const float* __restrict__ Wwp, const float* __restrict__ bwp,
        const float* __restrict__ Wop, const float* __restrict__ bop,
        const float* __restrict__ x, float* __restrict__ out) {
    extern __shared__ float sm[];
    float* smm  = sm;                      // [t][c] 64*132 (persists)
    float* sxn  = sm + 64 * 132;           // [i][t] 64*68 (phase 1)
    float* swpT = sm + 64 * 132 + 64 * 68; // [i][c] 64*132 (phase 1, +pad)
    float* sopT = sm + 64 * 132;           // [c][o] 128*68 (phase 2, reuse)
    int tid = threadIdx.x;
    long t0 = (long)blockIdx.x * 64;

    for (int idx = tid; idx < 64 * DM; idx += 256) {
        int c = idx & 127, t = idx >> 7;
        smm[t * 132 + c] = g_m[(t0 + t) * DM + c];
    }
    for (int idx = tid; idx < 64 * 64; idx += 256) {
        int i = idx & 63, t = idx >> 6;
        sxn[i * 68 + t] = g_xn[(t0 + t) * DMO + i];
    }
    for (int idx = tid; idx < DM * DMO; idx += 256) {
        int i = idx & 63, c = idx >> 6;
        swpT[i * 132 + c] = Wwp[c * DMO + i];
    }
    __syncthreads();
    int tx = tid & 31, ty = tid >> 5;
    {
        ull acc[4][4] = {};
        float4 w4 = *(const float4*)&swpT[tx << 2];
        ulonglong2 xa = *(const ulonglong2*)&sxn[ty * 8];
        ulonglong2 xb = *(const ulonglong2*)&sxn[ty * 8 + 4];
        #pragma unroll 8
        for (int i = 0; i < DMO; ++i) {
            ull wd0 = pk2(w4.x, w4.x), wd1 = pk2(w4.y, w4.y);
            ull wd2 = pk2(w4.z, w4.z), wd3 = pk2(w4.w, w4.w);
            ull x0 = xa.x, x1 = xa.y, x2 = xb.x, x3 = xb.y;
            w4 = *(const float4*)&swpT[(i + 1) * 132 + (tx << 2)];
            xa = *(const ulonglong2*)&sxn[(i + 1) * 68 + ty * 8];
            xb = *(const ulonglong2*)&sxn[(i + 1) * 68 + ty * 8 + 4];
            FMA16(acc, x0, x1, x2, x3, wd0, wd1, wd2, wd3);
        }
        float4 bq = *(const float4*)&bwp[tx << 2];
        float bj[4] = {bq.x, bq.y, bq.z, bq.w};
        #pragma unroll
        for (int p = 0; p < 4; ++p)
            #pragma unroll
            for (int j = 0; j < 4; ++j) {
                float2 v = upk(acc[p][j]);
                int c = (tx << 2) + j;
                int ta = ty * 8 + 2 * p;
                float va = v.x + bj[j], vb = v.y + bj[j];
                float wa = va / (1.f + __expf(-va));
                float wb = vb / (1.f + __expf(-vb));
                smm[ta * 132 + c] *= wa;
                smm[(ta + 1) * 132 + c] *= wb;
            }
    }
    __syncthreads();   // sxn/swpT dead -> load sopT
    for (int idx = tid; idx < DMO * DM; idx += 256) {
        int c = idx & 127, o = idx >> 7;
        sopT[c * 68 + o] = Wop[o * DM + c];
    }
    __syncthreads();
    {
        int rowg = tid >> 4;
        int o4 = (tid & 15) << 2;
        float a2[4][4] = {};
        for (int c = 0; c < DM; c += 4) {
            float4 q0 = *(const float4*)&sopT[(c + 0) * 68 + o4];
            float4 q1 = *(const float4*)&sopT[(c + 1) * 68 + o4];
            float4 q2 = *(const float4*)&sopT[(c + 2) * 68 + o4];
            float4 q3 = *(const float4*)&sopT[(c + 3) * 68 + o4];
            #pragma unroll
            for (int rr = 0; rr < 4; ++rr) {
                float4 pv = *(const float4*)&smm[(rowg * 4 + rr) * 132 + c];
                a2[rr][0] = fmaf(pv.x, q0.x, fmaf(pv.y, q1.x, fmaf(pv.z, q2.x, fmaf(pv.w, q3.x, a2[rr][0]))));
                a2[rr][1] = fmaf(pv.x, q0.y, fmaf(pv.y, q1.y, fmaf(pv.z, q2.y, fmaf(pv.w, q3.y, a2[rr][1]))));
                a2[rr][2] = fmaf(pv.x, q0.z, fmaf(pv.y, q1.z, fmaf(pv.z, q2.z, fmaf(pv.w, q3.z, a2[rr][2]))));
                a2[rr][3] = fmaf(pv.x, q0.w, fmaf(pv.y, q1.w, fmaf(pv.z, q2.w, fmaf(pv.w, q3.w, a2[rr][3]))));
            }
        }
        float4 bq = *(const float4*)&bop[o4];
        #pragma unroll
        for (int rr = 0; rr < 4; ++rr) {
            long tg = t0 + rowg * 4 + rr;
            float4 xq = *(const float4*)&x[tg * DMO + o4];
            float4 ov = make_float4(a2[rr][0] + bq.x + xq.x, a2[rr][1] + bq.y + xq.y,
                                    a2[rr][2] + bq.z + xq.z, a2[rr][3] + bq.w + xq.w);
            *(float4*)&out[tg * DMO + o4] = ov;
        }
    }
}

// ---------------- launch -----------------------------------------------------------
extern "C" void kernel_launch(void* const* d_in, const int* in_sizes, int n_in,
                              void* d_out, int out_size) {
    const float* x    = (const float*)d_in[0];
    const float* wn1  = (const float*)d_in[1];
    const float* wn2  = (const float*)d_in[2];
    const float* Wip  = (const float*)d_in[3];
    const float* bip  = (const float*)d_in[4];
    const float* Wfp  = (const float*)d_in[5];
    const float* bfp  = (const float*)d_in[6];
    const float* Wwp  = (const float*)d_in[7];
    const float* bwp  = (const float*)d_in[8];
    const float* Wop  = (const float*)d_in[9];
    const float* bop  = (const float*)d_in[10];
    const float* Win  = (const float*)d_in[11];
    const float* cw   = (const float*)d_in[12];
    const float* cb   = (const float*)d_in[13];
    const float* Xp   = (const float*)d_in[14];
    const float* Wdt  = (const float*)d_in[15];
    const float* bdt  = (const float*)d_in[16];
    const float* Alog = (const float*)d_in[17];
    const float* Dpar = (const float*)d_in[18];
    const float* Wmo  = (const float*)d_in[19];
    float* out = (float*)d_out;

    const int SM_K1 = (64 * 68 + 65 * 132 + 64 + 16) * 4;
    const int SM_K2 = (12800 + 140 + 128 + 16) * 4;
    const int SM_K4 = (2560 + 256 * 65) * 4;
    const int SM_K6 = (64 * 68 + 65 * 132 + 16) * 4;
    const int SM_K7 = (64 * 132 + 64 * 68 + 65 * 132 + 16) * 4;

    cudaFuncSetAttribute(k_rms_u,   cudaFuncAttributeMaxDynamicSharedMemorySize, SM_K1);
    cudaFuncSetAttribute(k_inproj,  cudaFuncAttributeMaxDynamicSharedMemorySize, SM_K2);
    cudaFuncSetAttribute(k_xproj,   cudaFuncAttributeMaxDynamicSharedMemorySize, SM_K4);
    cudaFuncSetAttribute(k_outproj, cudaFuncAttributeMaxDynamicSharedMemorySize, SM_K6);
    cudaFuncSetAttribute(k_final,   cudaFuncAttributeMaxDynamicSharedMemorySize, SM_K7);

    k_combine<<<32, 256>>>(Wfp, Wip, bip, bfp);
    k_combine2<<<128, 256>>>(Win);
    k_rms_u<<<TOK / 64, 256, SM_K1>>>(x, wn1);
    k_inproj<<<dim3(TOK / 64, 4), 256, SM_K2>>>(cw, cb);
    k_xproj<<<TOK / 64, 256, SM_K4>>>(Xp, Wdt, bdt);
    k_scan1<<<NUNIT / 16, 256>>>(Alog);
    k_scan2<<<64, 256>>>();
    k_scan3<<<NUNIT / 16, 256>>>(Alog, Dpar);
    k_outproj<<<TOK / 64, 256, SM_K6>>>(Wmo, wn2);
    k_final<<<TOK / 64, 256, SM_K7>>>(Wwp, bwp, Wop, bop, x, out);
}

// round 10
// speedup vs baseline: 2.0091x; 1.0529x over previous
#include <cuda_runtime.h>
#include <cstdint>

#define TOK 16384
#define LSEQ 4096
#define NB 4
#define DMO 64      // input/output dim D
#define DM 128      // d_model of mamba (2D)
#define DI 256      // d_inner
#define DS 16       // d_state
#define DTR 8       // dt_rank
#define NCH 1024    // NB * DI channels
#define CHK 64      // chunk length
#define NG (LSEQ / CHK)   // 64 chunks
#define NUNIT (NCH * NG)  // 65536 units

typedef unsigned long long ull;

__device__ __forceinline__ ull pk2(float a, float b) {
    ull r; asm("mov.b64 %0, {%1, %2};" : "=l"(r) : "f"(a), "f"(b)); return r;
}
__device__ __forceinline__ void fma2(ull& d, ull a, ull b) {
    asm("fma.rn.f32x2 %0, %1, %2, %3;" : "=l"(d) : "l"(a), "l"(b), "l"(d));
}
__device__ __forceinline__ float2 upk(ull v) {
    float2 r; asm("mov.b64 {%0, %1}, %2;" : "=f"(r.x), "=f"(r.y) : "l"(v)); return r;
}
__device__ __forceinline__ uint32_t tf32c(float f) {
    uint32_t r; asm("cvt.rna.tf32.f32 %0, %1;" : "=r"(r) : "f"(f)); return r;
}
#define MMA_TF32(c, a0, a1, a2, a3, b0, b1) \
    asm volatile("mma.sync.aligned.m16n8k8.row.col.f32.tf32.tf32.f32 " \
        "{%0,%1,%2,%3}, {%4,%5,%6,%7}, {%8,%9}, {%0,%1,%2,%3};" \
        : "+f"((c)[0]), "+f"((c)[1]), "+f"((c)[2]), "+f"((c)[3]) \
        : "r"(a0), "r"(a1), "r"(a2), "r"(a3), "r"(b0), "r"(b1))

// 16 packed FMAs: 4 tokens-pairs x 4 outputs
#define FMA16(acc, x0, x1, x2, x3, wd0, wd1, wd2, wd3) \
    fma2(acc[0][0], x0, wd0); fma2(acc[0][1], x0, wd1); fma2(acc[0][2], x0, wd2); fma2(acc[0][3], x0, wd3); \
    fma2(acc[1][0], x1, wd0); fma2(acc[1][1], x1, wd1); fma2(acc[1][2], x1, wd2); fma2(acc[1][3], x1, wd3); \
    fma2(acc[2][0], x2, wd0); fma2(acc[2][1], x2, wd1); fma2(acc[2][2], x2, wd2); fma2(acc[2][3], x2, wd3); \
    fma2(acc[3][0], x3, wd0); fma2(acc[3][1], x3, wd1); fma2(acc[3][2], x3, wd2); fma2(acc[3][3], x3, wd3)

// ---------------- scratch ----------------
// xc / zs / delta / y are CHANNEL-MAJOR: [(b*DI + d) * LSEQ + l]
__device__ float g_Wu[DM * DMO];      // W_fp @ W_ip
__device__ float g_bu[DM];            // W_fp @ b_ip + b_fp
__device__ float g_Wc[2 * DI * DMO];  // in_proj @ W_u   (512 x 64)
__device__ float g_bc[2 * DI];        // in_proj @ b_u
__device__ float g_xn[TOK * DMO];
__device__ float g_u[TOK * DM];
__device__ float g_xc[NCH * LSEQ];
__device__ float g_zs[NCH * LSEQ];
__device__ float g_delta[NCH * LSEQ];
__device__ float g_Bm[TOK * DS];
__device__ float g_Cm[TOK * DS];
__device__ float g_y[NCH * LSEQ];
__device__ float g_m[TOK * DM];
__device__ float g_P[NUNIT * DS];
__device__ float g_q[NUNIT * DS];
__device__ float g_hin[NUNIT * DS];

// ---------------- K0: compose W_u = W_fp @ W_ip, b_u = W_fp@b_ip + b_fp ----------
__global__ void k_combine(const float* __restrict__ Wfp, const float* __restrict__ Wip,
                          const float* __restrict__ bip, const float* __restrict__ bfp) {
    int idx = blockIdx.x * 256 + threadIdx.x;
    int o = idx / DMO, i = idx % DMO;
    float s = 0.f;
    for (int k = 0; k < DM; ++k) s = fmaf(Wfp[o * DM + k], Wip[k * DMO + i], s);
    g_Wu[idx] = s;
    if (blockIdx.x == 0 && threadIdx.x < DM) {
        int t = threadIdx.x;
        float sb = bfp[t];
        for (int k = 0; k < DM; ++k) sb = fmaf(Wfp[t * DM + k], bip[k], sb);
        g_bu[t] = sb;
    }
}

// ---------------- K0b: compose W_c = in_proj @ W_u, b_c = in_proj @ b_u ----------
__global__ void k_combine2(const float* __restrict__ Win) {
    int idx = blockIdx.x * 256 + threadIdx.x;   // 128 blocks -> 32768 = 512*64
    int e = idx >> 6, i = idx & 63;
    float s = 0.f;
    for (int k = 0; k < DM; ++k) s = fmaf(Win[(long)e * DM + k], g_Wu[k * DMO + i], s);
    g_Wc[idx] = s;
    if (i == 0) {
        float sb = 0.f;
        for (int k = 0; k < DM; ++k) sb = fmaf(Win[(long)e * DM + k], g_bu[k], sb);
        g_bc[e] = sb;
    }
}

// ---------------- K1: rmsnorm1 + u = W_u @ xn + b_u ------------------------------
__global__ void __launch_bounds__(256, 3)
k_rms_u(const float* __restrict__ x, const float* __restrict__ wn1) {
    extern __shared__ float sm[];
    float* sx  = sm;                 // 64*68 [i][t]
    float* swT = sm + 64 * 68;       // 64*132 [i][o]  (+pad row for prefetch)
    float* ssc = swT + 65 * 132;     // 64
    int tid = threadIdx.x;
    long t0 = (long)blockIdx.x * 64;

    for (int idx = tid; idx < 64 * 64; idx += 256) {
        int i = idx & 63, t = idx >> 6;
        sx[i * 68 + t] = x[(t0 + t) * DMO + i];
    }
    for (int idx = tid; idx < DM * DMO; idx += 256) {
        int i = idx & 63, o = idx >> 6;
        swT[i * 132 + o] = g_Wu[o * DMO + i];
    }
    __syncthreads();
    if (tid < 64) {
        float ss = 0.f;
        for (int i = 0; i < DMO; ++i) { float v = sx[i * 68 + tid]; ss = fmaf(v, v, ss); }
        ssc[tid] = rsqrtf(ss * (1.f / DMO) + 1e-5f);
    }
    __syncthreads();
    for (int idx = tid; idx < 64 * 64; idx += 256) {
        int i = idx & 63, t = idx >> 6;
        float v = sx[i * 68 + t] * ssc[t] * wn1[i];
        sx[i * 68 + t] = v;
        g_xn[(t0 + t) * DMO + i] = v;
    }
    __syncthreads();
    int tx = tid & 31, ty = tid >> 5;
    ull acc[4][4] = {};
    float4 w4 = *(const float4*)&swT[tx << 2];
    ulonglong2 xa = *(const ulonglong2*)&sx[ty * 8];
    ulonglong2 xb = *(const ulonglong2*)&sx[ty * 8 + 4];
    #pragma unroll 8
    for (int i = 0; i < DMO; ++i) {
        ull wd0 = pk2(w4.x, w4.x), wd1 = pk2(w4.y, w4.y);
        ull wd2 = pk2(w4.z, w4.z), wd3 = pk2(w4.w, w4.w);
        ull x0 = xa.x, x1 = xa.y, x2 = xb.x, x3 = xb.y;
        w4 = *(const float4*)&swT[(i + 1) * 132 + (tx << 2)];
        xa = *(const ulonglong2*)&sx[(i + 1) * 68 + ty * 8];
        xb = *(const ulonglong2*)&sx[(i + 1) * 68 + ty * 8 + 4];
        FMA16(acc, x0, x1, x2, x3, wd0, wd1, wd2, wd3);
    }
    float4 bq = *(const float4*)&g_bu[tx << 2];
    #pragma unroll
    for (int p = 0; p < 4; ++p) {
        float2 v0 = upk(acc[p][0]), v1 = upk(acc[p][1]), v2 = upk(acc[p][2]), v3 = upk(acc[p][3]);
        long ta = t0 + ty * 8 + 2 * p, tb = ta + 1;
        float4 lo = make_float4(v0.x + bq.x, v1.x + bq.y, v2.x + bq.z, v3.x + bq.w);
        float4 hi = make_float4(v0.y + bq.x, v1.y + bq.y, v2.y + bq.z, v3.y + bq.w);
        *(float4*)&g_u[ta * DM + (tx << 2)] = lo;
        *(float4*)&g_u[tb * DM + (tx << 2)] = hi;
    }
}

// ---------------- K2: xz = W_c @ xn + b_c (tf32 MMA) ; fused conv+silu / silu ----
__global__ void __launch_bounds__(256, 3)
k_inproj(const float* __restrict__ cw, const float* __restrict__ cb) {
    extern __shared__ float sm[];
    float* sxn   = sm;                 // [i][t] 64*68 ; cols 0-63 main, 64-66 halo
    float* swT   = sm + 64 * 68;       // [i][e] 64*132
    float* sbc   = sm + 12800 + 140;   // 128 biases (persists)
    float* stage = sm;                 // [e][t'] 128*68 AFTER GEMM (reuse)
    int tid = threadIdx.x;
    long t0 = (long)blockIdx.x * 64;
    int e0 = blockIdx.y * 128;
    int b = (int)(t0 >> 12);
    int l0 = (int)(t0 & (LSEQ - 1));
    bool isx = (e0 < DI);

    for (int idx = tid; idx < 64 * 64; idx += 256) {
        int i = idx & 63, t = idx >> 6;
        sxn[i * 68 + t] = g_xn[(t0 + t) * DMO + i];
    }
    for (int idx = tid; idx < 128 * 64; idx += 256) {
        int i = idx & 63, e = idx >> 6;
        swT[i * 132 + e] = g_Wc[(long)(e0 + e) * DMO + i];
    }
    if (tid < 128) sbc[tid] = g_bc[e0 + tid];
    if (isx && tid < 192) {   // halo xn: tokens t0-3..t0-1
        int i = tid & 63, j = tid >> 6;
        sxn[i * 68 + 64 + j] = (l0 > 0) ? g_xn[(t0 - 3 + j) * DMO + i] : 0.f;
    }
    __syncthreads();
    int warp = tid >> 5, lane = tid & 31, g = lane >> 2, tg = lane & 3;
    int ew = warp * 16;
    float c[8][4] = {};
    #pragma unroll
    for (int ks = 0; ks < 8; ++ks) {
        int kk = ks * 8;
        uint32_t a0 = tf32c(swT[(kk + tg) * 132 + ew + g]);
        uint32_t a1 = tf32c(swT[(kk + tg) * 132 + ew + g + 8]);
        uint32_t a2 = tf32c(swT[(kk + tg + 4) * 132 + ew + g]);
        uint32_t a3 = tf32c(swT[(kk + tg + 4) * 132 + ew + g + 8]);
        #pragma unroll
        for (int nt = 0; nt < 8; ++nt) {
            uint32_t b0 = tf32c(sxn[(kk + tg) * 68 + nt * 8 + g]);
            uint32_t b1 = tf32c(sxn[(kk + tg + 4) * 68 + nt * 8 + g]);
            MMA_TF32(c[nt], a0, a1, a2, a3, b0, b1);
        }
    }
    // halo xz values -> registers (x blocks only)
    float h1 = 0.f, h2 = 0.f;
    if (isx && l0 > 0) {
        {
            int j = tid >> 7, e = tid & 127;
            float a = sbc[e];
            for (int i = 0; i < 64; ++i)
                a = fmaf(sxn[i * 68 + 64 + j], swT[i * 132 + e], a);
            h1 = a;
        }
        if (tid < 128) {
            int e = tid;
            float a = sbc[e];
            for (int i = 0; i < 64; ++i)
                a = fmaf(sxn[i * 68 + 66], swT[i * 132 + e], a);
            h2 = a;
        }
    }
    __syncthreads();   // all reads of sxn/swT done -> reuse as stage
    {
        float bc0 = sbc[ew + g], bc1 = sbc[ew + g + 8];
        #pragma unroll
        for (int nt = 0; nt < 8; ++nt) {
            int t = nt * 8 + 2 * tg;
            stage[(ew + g) * 68 + 3 + t]     = c[nt][0] + bc0;
            stage[(ew + g) * 68 + 4 + t]     = c[nt][1] + bc0;
            stage[(ew + g + 8) * 68 + 3 + t] = c[nt][2] + bc1;
            stage[(ew + g + 8) * 68 + 4 + t] = c[nt][3] + bc1;
        }
    }
    if (isx) {
        { int j = tid >> 7, e = tid & 127; stage[e * 68 + j] = h1; }
        if (tid < 128) stage[tid * 68 + 2] = h2;
    }
    __syncthreads();
    if (isx) {
        for (int idx = tid; idx < 128 * 64; idx += 256) {
            int t = idx & 63, e = idx >> 6;
            int d = e0 + e;
            const float* st = &stage[e * 68];
            float4 w = *(const float4*)&cw[d * 4];
            float a = cb[d];
            a = fmaf(w.x, st[t], a);
            a = fmaf(w.y, st[t + 1], a);
            a = fmaf(w.z, st[t + 2], a);
            a = fmaf(w.w, st[t + 3], a);
            a = a / (1.f + __expf(-a));
            g_xc[(long)(b * DI + d) * LSEQ + l0 + t] = a;
        }
    } else {
        for (int idx = tid; idx < 128 * 64; idx += 256) {
            int t = idx & 63, e = idx >> 6;
            float v = stage[e * 68 + 3 + t];
            v = v / (1.f + __expf(-v));
            g_zs[(long)(b * DI + (e0 - DI) + e) * LSEQ + l0 + t] = v;
        }
    }
}

// ---------------- K4: x_dbl = x_proj @ x ; B,C ; delta (K-chunked, smem reuse) ---
__global__ void __launch_bounds__(256, 2)
k_xproj(const float* __restrict__ Xp, const float* __restrict__ Wdt,
        const float* __restrict__ bdt) {
    extern __shared__ float sm[];
    float* sdbl = sm;                 // 64*40 (persists)
    float* sxc  = sm + 2560;          // phase1: [t][kk] 64*132
    float* spc  = sm + 2560 + 8448;   // phase1: [e][kk] 40*132
    float* sdel = sm + 2560;          // phase2: [d][t] 256*65 (reuses chunk region)
    int tid = threadIdx.x;
    long t0 = (long)blockIdx.x * 64;
    int b = (int)(t0 >> 12);
    int l0 = (int)(t0 & (LSEQ - 1));

    int tt = tid >> 2, eb = (tid & 3) * 10;
    float acc[10] = {};
    for (int kc = 0; kc < 2; ++kc) {
        __syncthreads();
        for (int idx = tid; idx < 64 * 128; idx += 256) {
            int t = idx & 63, kk = idx >> 6;
            sxc[t * 132 + kk] = g_xc[(long)(b * DI + kc * 128 + kk) * LSEQ + l0 + t];
        }
        for (int idx = tid; idx < 40 * 128; idx += 256) {
            int kk = idx & 127, e = idx >> 7;
            spc[e * 132 + kk] = Xp[e * DI + kc * 128 + kk];
        }
        __syncthreads();
        for (int kk = 0; kk < 128; kk += 4) {
            float4 xv = *(const float4*)&sxc[tt * 132 + kk];
            #pragma unroll
            for (int e = 0; e < 10; ++e) {
                float4 wv = *(const float4*)&spc[(eb + e) * 132 + kk];
                acc[e] = fmaf(xv.x, wv.x, fmaf(xv.y, wv.y, fmaf(xv.z, wv.z, fmaf(xv.w, wv.w, acc[e]))));
            }
        }
    }
    __syncthreads();
    #pragma unroll
    for (int e = 0; e < 10; ++e) sdbl[tt * 40 + eb + e] = acc[e];
    __syncthreads();
    for (int idx = tid; idx < 64 * DS; idx += 256) {
        int t = idx >> 4, s = idx & 15;
        g_Bm[(t0 + t) * DS + s] = sdbl[t * 40 + 8 + s];
        g_Cm[(t0 + t) * DS + s] = sdbl[t * 40 + 24 + s];
    }
    {
        int d = tid;
        float wr[8];
        #pragma unroll
        for (int r = 0; r < 8; ++r) wr[r] = Wdt[d * 8 + r];
        float bb = bdt[d];
        for (int t = 0; t < 64; ++t) {
            float pre = bb;
            #pragma unroll
            for (int r = 0; r < 8; ++r) pre = fmaf(sdbl[t * 40 + r], wr[r], pre);
            float sp = (pre > 20.f) ? pre : log1pf(__expf(pre));
            sdel[d * 65 + t] = sp;
        }
    }
    __syncthreads();
    for (int idx = tid; idx < DI * 64; idx += 256) {
        int d = idx >> 6, t = idx & 63;
        g_delta[(long)(b * DI + d) * LSEQ + l0 + t] = sdel[d * 65 + t];
    }
}

// ---------------- K5a: per-chunk decay product P and local state q ----------------
__global__ void __launch_bounds__(256, 6)
k_scan1(const float* __restrict__ Alog) {
    int u = threadIdx.x >> 4;
    int s = threadIdx.x & 15;
    int unit = blockIdx.x * 16 + u;
    int g = unit & (NG - 1);
    int ch = unit >> 6;
    int b = ch >> 8, d = ch & 255;
    float Aval = -__expf(Alog[d * DS + s]);
    const float* pd = g_delta + (long)ch * LSEQ + g * CHK;
    const float* px = g_xc    + (long)ch * LSEQ + g * CHK;
    const float* pB = g_Bm    + ((long)b * LSEQ + g * CHK) * DS + s;
    float P = 1.f, q = 0.f;
    #pragma unroll 4
    for (int t = 0; t < CHK; t += 4) {
        float4 dv = *(const float4*)&pd[t];
        float4 xv = *(const float4*)&px[t];
        float B0 = pB[(t + 0) * DS], B1 = pB[(t + 1) * DS];
        float B2 = pB[(t + 2) * DS], B3 = pB[(t + 3) * DS];
        float a0 = __expf(dv.x * Aval); P *= a0; q = fmaf(a0, q, dv.x * xv.x * B0);
        float a1 = __expf(dv.y * Aval); P *= a1; q = fmaf(a1, q, dv.y * xv.y * B1);
        float a2 = __expf(dv.z * Aval); P *= a2; q = fmaf(a2, q, dv.z * xv.z * B2);
        float a3 = __expf(dv.w * Aval); P *= a3; q = fmaf(a3, q, dv.w * xv.w * B3);
    }
    long idx = (long)unit * DS + s;
    g_P[idx] = P;
    g_q[idx] = q;
}

// ---------------- K5b: propagate h_in across chunks ------------------------------
__global__ void k_scan2() {
    int tid = blockIdx.x * 256 + threadIdx.x;
    int ch = tid >> 4, s = tid & 15;
    float h = 0.f;
    long base = (long)ch * NG * DS + s;
    #pragma unroll 8
    for (int g = 0; g < NG; ++g) {
        long idx = base + (long)g * DS;
        g_hin[idx] = h;
        h = fmaf(g_P[idx], h, g_q[idx]);
    }
}

// ---------------- K5c: local scan from h_in, y = (C.h + x*D) * silu(z) -----------
__global__ void __launch_bounds__(256, 6)
k_scan3(const float* __restrict__ Alog, const float* __restrict__ Dp_) {
    __shared__ float ybuf[16 * CHK];
    int u = threadIdx.x >> 4;
    int s = threadIdx.x & 15;
    int unit = blockIdx.x * 16 + u;
    int g = unit & (NG - 1);
    int ch = unit >> 6;
    int b = ch >> 8, d = ch & 255;
    float Aval = -__expf(Alog[d * DS + s]);
    float Dp = Dp_[d];
    const float* pd = g_delta + (long)ch * LSEQ + g * CHK;
    const float* px = g_xc    + (long)ch * LSEQ + g * CHK;
    const float* pz = g_zs    + (long)ch * LSEQ + g * CHK;
    const float* pB = g_Bm    + ((long)b * LSEQ + g * CHK) * DS + s;
    const float* pC = g_Cm    + ((long)b * LSEQ + g * CHK) * DS + s;
    float h = g_hin[(long)unit * DS + s];
    #pragma unroll 2
    for (int t = 0; t < CHK; t += 4) {
        float4 dv = *(const float4*)&pd[t];
        float4 xv = *(const float4*)&px[t];
        float4 zv;
        if (s == 0) zv = *(const float4*)&pz[t];
        #pragma unroll
        for (int j = 0; j < 4; ++j) {
            float dvj = (j == 0) ? dv.x : (j == 1) ? dv.y : (j == 2) ? dv.z : dv.w;
            float xvj = (j == 0) ? xv.x : (j == 1) ? xv.y : (j == 2) ? xv.z : xv.w;
            float Bv = pB[(t + j) * DS];
            float Cv = pC[(t + j) * DS];
            float a = __expf(dvj * Aval);
            h = fmaf(a, h, dvj * xvj * Bv);
            float p = h * Cv;
            p += __shfl_xor_sync(0xffffffffu, p, 8);
            p += __shfl_xor_sync(0xffffffffu, p, 4);
            p += __shfl_xor_sync(0xffffffffu, p, 2);
            p += __shfl_xor_sync(0xffffffffu, p, 1);
            if (s == 0) {
                float zvj = (j == 0) ? zv.x : (j == 1) ? zv.y : (j == 2) ? zv.z : zv.w;
                ybuf[u * CHK + t + j] = (p + xvj * Dp) * zvj;
            }
        }
    }
    __syncthreads();
    float* py = g_y + (long)ch * LSEQ + (long)(blockIdx.x & 3) * 1024;
    for (int i = threadIdx.x; i < 16 * CHK; i += 256) py[i] = ybuf[i];
}

// ---------------- K6: m = rmsnorm2(mamba_out @ y) + u (tf32 MMA, K-chunked) ------
__global__ void __launch_bounds__(256, 3)
k_outproj(const float* __restrict__ Wmo, const float* __restrict__ wn2) {
    extern __shared__ float sm[];
    float* syT = sm;               // [k][t] 64*68 chunk
    float* swT = sm + 64 * 68;     // [k][o] 64*132 chunk ; later stage [t][o] 64*132
    int tid = threadIdx.x;
    long t0 = (long)blockIdx.x * 64;
    int b = (int)(t0 >> 12);
    int lpos = (int)(t0 & (LSEQ - 1));
    int warp = tid >> 5, lane = tid & 31, g = lane >> 2, tg = lane & 3;
    int o0 = warp * 16;

    float c[8][4] = {};
    for (int kc = 0; kc < 4; ++kc) {
        __syncthreads();
        for (int idx = tid; idx < 64 * 16; idx += 256) {
            int t4 = idx & 15, k = idx >> 4;
            *(float4*)&syT[k * 68 + t4 * 4] =
                *(const float4*)&g_y[(long)(b * DI + kc * 64 + k) * LSEQ + lpos + t4 * 4];
        }
        for (int idx = tid; idx < 64 * DM; idx += 256) {
            int k = idx & 63, o = idx >> 6;
            swT[k * 132 + o] = Wmo[(long)o * DI + kc * 64 + k];
        }
        __syncthreads();
        #pragma unroll
        for (int ks = 0; ks < 8; ++ks) {
            int kk = ks * 8;
            uint32_t a0 = tf32c(swT[(kk + tg) * 132 + o0 + g]);
            uint32_t a1 = tf32c(swT[(kk + tg) * 132 + o0 + g + 8]);
            uint32_t a2 = tf32c(swT[(kk + tg + 4) * 132 + o0 + g]);
            uint32_t a3 = tf32c(swT[(kk + tg + 4) * 132 + o0 + g + 8]);
            #pragma unroll
            for (int nt = 0; nt < 8; ++nt) {
                uint32_t b0 = tf32c(syT[(kk + tg) * 68 + nt * 8 + g]);
                uint32_t b1 = tf32c(syT[(kk + tg + 4) * 68 + nt * 8 + g]);
                MMA_TF32(c[nt], a0, a1, a2, a3, b0, b1);
            }
        }
    }
    __syncthreads();   // swT reads done -> reuse as [t][o] stage
    float* stage = swT;
    #pragma unroll
    for (int nt = 0; nt < 8; ++nt) {
        int t = nt * 8 + 2 * tg;
        stage[t * 132 + o0 + g]           = c[nt][0];
        stage[(t + 1) * 132 + o0 + g]     = c[nt][1];
        stage[t * 132 + o0 + g + 8]       = c[nt][2];
        stage[(t + 1) * 132 + o0 + g + 8] = c[nt][3];
    }
    __syncthreads();
    {
        int t = tid >> 2, part = tid & 3;
        int ob = part * 32;
        float ss = 0.f;
        #pragma unroll
        for (int j = 0; j < 32; j += 4) {
            float4 v = *(const float4*)&stage[t * 132 + ob + j];
            ss = fmaf(v.x, v.x, fmaf(v.y, v.y, fmaf(v.z, v.z, fmaf(v.w, v.w, ss))));
        }
        ss += __shfl_xor_sync(0xffffffffu, ss, 1);
        ss += __shfl_xor_sync(0xffffffffu, ss, 2);
        float sc = rsqrtf(ss * (1.f / DM) + 1e-5f);
        long tt = t0 + t;
        #pragma unroll
        for (int j = 0; j < 32; j += 4) {
            float4 v  = *(const float4*)&stage[t * 132 + ob + j];
            float4 w2 = *(const float4*)&wn2[ob + j];
            float4 uq = *(const float4*)&g_u[tt * DM + ob + j];
            float4 ov = make_float4(v.x * sc * w2.x + uq.x, v.y * sc * w2.y + uq.y,
                                    v.z * sc * w2.z + uq.z, v.w * sc * w2.w + uq.w);
            *(float4*)&g_m[tt * DM + ob + j] = ov;
        }
    }
}

// ---------------- K7: w = swish(W_wp@xn+b) ; out = W_op@(w*m)+b + x ---------------
__global__ void __launch_bounds__(256, 2)
k_final(const float* __restrict__ Wwp, const float* __restrict__ bwp,
        const float* __restrict__ Wop, const float* __restrict__ bop,
        const float* __restrict__ x, float* __restrict__ out) {
    extern __shared__ float sm[];
    float* smm  = sm;                      // [t][c] 64*132 (persists)
    float* sxn  = sm + 64 * 132;           // [i][t] 64*68 (phase 1)
    float* swpT = sm + 64 * 132 + 64 * 68; // [i][c] 64*132 (phase 1, +pad)
    float* sopT = sm + 64 * 132;           // [c][o] 128*68 (phase 2, reuse)
    int tid = threadIdx.x;
    long t0 = (long)blockIdx.x * 64;

    for (int idx = tid; idx < 64 * DM; idx += 256) {
        int c = idx & 127, t = idx >> 7;
        smm[t * 132 + c] = g_m[(t0 + t) * DM + c];
    }
    for (int idx = tid; idx < 64 * 64; idx += 256) {
        int i = idx & 63, t = idx >> 6;
        sxn[i * 68 + t] = g_xn[(t0 + t) * DMO + i];
    }
    for (int idx = tid; idx < DM * DMO; idx += 256) {
        int i = idx & 63, c = idx >> 6;
        swpT[i * 132 + c] = Wwp[c * DMO + i];
    }
    __syncthreads();
    int tx = tid & 31, ty = tid >> 5;
    {
        ull acc[4][4] = {};
        float4 w4 = *(const float4*)&swpT[tx << 2];
        ulonglong2 xa = *(const ulonglong2*)&sxn[ty * 8];
        ulonglong2 xb = *(const ulonglong2*)&sxn[ty * 8 + 4];
        #pragma unroll 8
        for (int i = 0; i < DMO; ++i) {
            ull wd0 = pk2(w4.x, w4.x), wd1 = pk2(w4.y, w4.y);
            ull wd2 = pk2(w4.z, w4.z), wd3 = pk2(w4.w, w4.w);
            ull x0 = xa.x, x1 = xa.y, x2 = xb.x, x3 = xb.y;
            w4 = *(const float4*)&swpT[(i + 1) * 132 + (tx << 2)];
            xa = *(const ulonglong2*)&sxn[(i + 1) * 68 + ty * 8];
            xb = *(const ulonglong2*)&sxn[(i + 1) * 68 + ty * 8 + 4];
            FMA16(acc, x0, x1, x2, x3, wd0, wd1, wd2, wd3);
        }
        float4 bq = *(const float4*)&bwp[tx << 2];
        float bj[4] = {bq.x, bq.y, bq.z, bq.w};
        #pragma unroll
        for (int p = 0; p < 4; ++p)
            #pragma unroll
            for (int j = 0; j < 4; ++j) {
                float2 v = upk(acc[p][j]);
                int c = (tx << 2) + j;
                int ta = ty * 8 + 2 * p;
                float va = v.x + bj[j], vb = v.y + bj[j];
                float wa = va / (1.f + __expf(-va));
                float wb = vb / (1.f + __expf(-vb));
                smm[ta * 132 + c] *= wa;
                smm[(ta + 1) * 132 + c] *= wb;
            }
    }
    __syncthreads();   // sxn/swpT dead -> load sopT
    for (int idx = tid; idx < DMO * DM; idx += 256) {
        int c = idx & 127, o = idx >> 7;
        sopT[c * 68 + o] = Wop[o * DM + c];
    }
    __syncthreads();
    {
        int rowg = tid >> 4;
        int o4 = (tid & 15) << 2;
        float a2[4][4] = {};
        for (int c = 0; c < DM; c += 4) {
            float4 q0 = *(const float4*)&sopT[(c + 0) * 68 + o4];
            float4 q1 = *(const float4*)&sopT[(c + 1) * 68 + o4];
            float4 q2 = *(const float4*)&sopT[(c + 2) * 68 + o4];
            float4 q3 = *(const float4*)&sopT[(c + 3) * 68 + o4];
            #pragma unroll
            for (int rr = 0; rr < 4; ++rr) {
                float4 pv = *(const float4*)&smm[(rowg * 4 + rr) * 132 + c];
                a2[rr][0] = fmaf(pv.x, q0.x, fmaf(pv.y, q1.x, fmaf(pv.z, q2.x, fmaf(pv.w, q3.x, a2[rr][0]))));
                a2[rr][1] = fmaf(pv.x, q0.y, fmaf(pv.y, q1.y, fmaf(pv.z, q2.y, fmaf(pv.w, q3.y, a2[rr][1]))));
                a2[rr][2] = fmaf(pv.x, q0.z, fmaf(pv.y, q1.z, fmaf(pv.z, q2.z, fmaf(pv.w, q3.z, a2[rr][2]))));
                a2[rr][3] = fmaf(pv.x, q0.w, fmaf(pv.y, q1.w, fmaf(pv.z, q2.w, fmaf(pv.w, q3.w, a2[rr][3]))));
            }
        }
        float4 bq = *(const float4*)&bop[o4];
        #pragma unroll
        for (int rr = 0; rr < 4; ++rr) {
            long tg = t0 + rowg * 4 + rr;
            float4 xq = *(const float4*)&x[tg * DMO + o4];
            float4 ov = make_float4(a2[rr][0] + bq.x + xq.x, a2[rr][1] + bq.y + xq.y,
                                    a2[rr][2] + bq.z + xq.z, a2[rr][3] + bq.w + xq.w);
            *(float4*)&out[tg * DMO + o4] = ov;
        }
    }
}

// ---------------- launch -----------------------------------------------------------
extern "C" void kernel_launch(void* const* d_in, const int* in_sizes, int n_in,
                              void* d_out, int out_size) {
    const float* x    = (const float*)d_in[0];
    const float* wn1  = (const float*)d_in[1];
    const float* wn2  = (const float*)d_in[2];
    const float* Wip  = (const float*)d_in[3];
    const float* bip  = (const float*)d_in[4];
    const float* Wfp  = (const float*)d_in[5];
    const float* bfp  = (const float*)d_in[6];
    const float* Wwp  = (const float*)d_in[7];
    const float* bwp  = (const float*)d_in[8];
    const float* Wop  = (const float*)d_in[9];
    const float* bop  = (const float*)d_in[10];
    const float* Win  = (const float*)d_in[11];
    const float* cw   = (const float*)d_in[12];
    const float* cb   = (const float*)d_in[13];
    const float* Xp   = (const float*)d_in[14];
    const float* Wdt  = (const float*)d_in[15];
    const float* bdt  = (const float*)d_in[16];
    const float* Alog = (const float*)d_in[17];
    const float* Dpar = (const float*)d_in[18];
    const float* Wmo  = (const float*)d_in[19];
    float* out = (float*)d_out;

    const int SM_K1 = (64 * 68 + 65 * 132 + 64 + 16) * 4;
    const int SM_K2 = (12800 + 140 + 128 + 16) * 4;
    const int SM_K4 = (2560 + 256 * 65) * 4;
    const int SM_K6 = (64 * 68 + 64 * 132) * 4;
    const int SM_K7 = (64 * 132 + 64 * 68 + 65 * 132 + 16) * 4;

    cudaFuncSetAttribute(k_rms_u,   cudaFuncAttributeMaxDynamicSharedMemorySize, SM_K1);
    cudaFuncSetAttribute(k_inproj,  cudaFuncAttributeMaxDynamicSharedMemorySize, SM_K2);
    cudaFuncSetAttribute(k_xproj,   cudaFuncAttributeMaxDynamicSharedMemorySize, SM_K4);
    cudaFuncSetAttribute(k_outproj, cudaFuncAttributeMaxDynamicSharedMemorySize, SM_K6);
    cudaFuncSetAttribute(k_final,   cudaFuncAttributeMaxDynamicSharedMemorySize, SM_K7);

    k_combine<<<32, 256>>>(Wfp, Wip, bip, bfp);
    k_combine2<<<128, 256>>>(Win);
    k_rms_u<<<TOK / 64, 256, SM_K1>>>(x, wn1);
    k_inproj<<<dim3(TOK / 64, 4), 256, SM_K2>>>(cw, cb);
    k_xproj<<<TOK / 64, 256, SM_K4>>>(Xp, Wdt, bdt);
    k_scan1<<<NUNIT / 16, 256>>>(Alog);
    k_scan2<<<64, 256>>>();
    k_scan3<<<NUNIT / 16, 256>>>(Alog, Dpar);
    k_outproj<<<TOK / 64, 256, SM_K6>>>(Wmo, wn2);
    k_final<<<TOK / 64, 256, SM_K7>>>(Wwp, bwp, Wop, bop, x, out);
}